// round 5
// baseline (speedup 1.0000x reference)
#include <cuda_runtime.h>
#include <cuda_bf16.h>
#include <cstdint>

// Problem constants
#define DIMM   2048
#define HN     16
#define HDIM   128
#define BB     2
#define NN     2048
#define E3     (3 * HN * HDIM)      // 6144
#define MROWS  (BB * NN)            // 4096
#define EPSV   1e-5f
#define QSCALE 0.08838834764831845f // 1/sqrt(128)

// ---------------- scratch (static device arrays; no allocation) -------------
__device__ float g_qkv[(size_t)MROWS * E3];

__device__ __nv_bfloat16 g_qhi[(size_t)BB * HN * NN * HDIM];
__device__ __nv_bfloat16 g_qlo[(size_t)BB * HN * NN * HDIM];
__device__ __nv_bfloat16 g_khi[(size_t)BB * HN * NN * HDIM];
__device__ __nv_bfloat16 g_klo[(size_t)BB * HN * NN * HDIM];
__device__ __nv_bfloat16 g_vhi[(size_t)BB * HN * NN * HDIM];
__device__ __nv_bfloat16 g_vlo[(size_t)BB * HN * NN * HDIM];

__device__ __nv_bfloat16 g_xhi[(size_t)MROWS * DIMM];
__device__ __nv_bfloat16 g_xlo[(size_t)MROWS * DIMM];
__device__ __nv_bfloat16 g_w1hi[(size_t)E3 * DIMM];
__device__ __nv_bfloat16 g_w1lo[(size_t)E3 * DIMM];
__device__ __nv_bfloat16 g_w2hi[(size_t)DIMM * DIMM];
__device__ __nv_bfloat16 g_w2lo[(size_t)DIMM * DIMM];
__device__ __nv_bfloat16 g_aohi[(size_t)MROWS * DIMM];
__device__ __nv_bfloat16 g_aolo[(size_t)MROWS * DIMM];

// ============================================================================
// helpers
// ============================================================================
__device__ __forceinline__ uint32_t smem_u32(const void* p) {
    uint32_t a;
    asm("{ .reg .u64 t; cvta.to.shared.u64 t, %1; cvt.u32.u64 %0, t; }"
        : "=r"(a) : "l"(p));
    return a;
}
__device__ __forceinline__ void cp_async16(uint32_t dst, const void* src) {
    asm volatile("cp.async.cg.shared.global [%0], [%1], 16;"
                 :: "r"(dst), "l"(src));
}
#define CP_COMMIT() asm volatile("cp.async.commit_group;" ::: "memory")
#define CP_WAIT(n)  asm volatile("cp.async.wait_group %0;" :: "n"(n) : "memory")

__device__ __forceinline__ void ldsm_x4(uint32_t* r, uint32_t addr) {
    asm volatile("ldmatrix.sync.aligned.m8n8.x4.shared.b16 {%0,%1,%2,%3}, [%4];"
                 : "=r"(r[0]), "=r"(r[1]), "=r"(r[2]), "=r"(r[3]) : "r"(addr));
}
__device__ __forceinline__ void ldsm_x4_t(uint32_t* r, uint32_t addr) {
    asm volatile("ldmatrix.sync.aligned.m8n8.x4.trans.shared.b16 {%0,%1,%2,%3}, [%4];"
                 : "=r"(r[0]), "=r"(r[1]), "=r"(r[2]), "=r"(r[3]) : "r"(addr));
}
__device__ __forceinline__ void mma_bf16(float* c, const uint32_t* a,
                                         const uint32_t* b) {
    asm volatile(
        "mma.sync.aligned.m16n8k16.row.col.f32.bf16.bf16.f32 "
        "{%0,%1,%2,%3}, {%4,%5,%6,%7}, {%8,%9}, {%0,%1,%2,%3};"
        : "+f"(c[0]), "+f"(c[1]), "+f"(c[2]), "+f"(c[3])
        : "r"(a[0]), "r"(a[1]), "r"(a[2]), "r"(a[3]), "r"(b[0]), "r"(b[1]));
}
__device__ __forceinline__ void split2(float x, float y, uint32_t& hi, uint32_t& lo) {
    __nv_bfloat16 hx = __float2bfloat16(x), hy = __float2bfloat16(y);
    float rx = x - __bfloat162float(hx), ry = y - __bfloat162float(hy);
    __nv_bfloat162 H; H.x = hx; H.y = hy;
    __nv_bfloat162 L; L.x = __float2bfloat16(rx); L.y = __float2bfloat16(ry);
    hi = *(uint32_t*)&H;
    lo = *(uint32_t*)&L;
}

// ============================================================================
// fp32 -> bf16 hi/lo split
// ============================================================================
__global__ void __launch_bounds__(256) split_bf16(
    const float* __restrict__ in, __nv_bfloat16* __restrict__ hi,
    __nv_bfloat16* __restrict__ lo, int n4)
{
    int i = blockIdx.x * 256 + threadIdx.x;
    if (i >= n4) return;
    float4 v = ((const float4*)in)[i];
    union { __nv_bfloat16 b[4]; uint2 u; } H, L;
    float vv[4] = {v.x, v.y, v.z, v.w};
#pragma unroll
    for (int j = 0; j < 4; j++) {
        __nv_bfloat16 h = __float2bfloat16(vv[j]);
        H.b[j] = h;
        L.b[j] = __float2bfloat16(vv[j] - __bfloat162float(h));
    }
    ((uint2*)hi)[i] = H.u;
    ((uint2*)lo)[i] = L.u;
}

// ============================================================================
// bf16 split GEMM v2: CTA 256x128, BK=32, 8 warps (4x2), warp tile 64x64,
// 3-stage cp.async pipeline, pass-reordered mma (no back-to-back RAW on acc).
// ============================================================================
#define SA 40
#define A_MAT (256 * SA * 2)          // 20480
#define B_MAT (128 * SA * 2)          // 10240
#define STAGE2 (2 * A_MAT + 2 * B_MAT) // 61440
#define GEMM_SMEM (3 * STAGE2)         // 184320

__global__ void __launch_bounds__(256, 1) gemm_mma_split(
    const __nv_bfloat16* __restrict__ Ah, const __nv_bfloat16* __restrict__ Al,
    const __nv_bfloat16* __restrict__ Bh, const __nv_bfloat16* __restrict__ Bl,
    float* __restrict__ C, int Ntot, int K)
{
    extern __shared__ __align__(128) char sm[];
    const uint32_t sbase = smem_u32(sm);
    const int tid = threadIdx.x;
    const int lane = tid & 31;
    const int wid = tid >> 5;
    const int warp_m = wid & 3;        // 4 warps over M: 64 rows each
    const int warp_n = wid >> 2;       // 2 warps over N: 64 cols each
    const int bm = blockIdx.y * 256;
    const int bn = blockIdx.x * 128;

    // stage loader: 3072 16B chunks (A hi/lo 2048, B hi/lo 1024), 12/thread
    auto issue_stage = [&](int stage, int kc) {
        uint32_t sdst = sbase + stage * STAGE2;
#pragma unroll
        for (int t = 0; t < 12; t++) {
            int idx = tid + t * 256;
            uint32_t dst;
            const __nv_bfloat16* src;
            if (idx < 2048) {
                int mat = idx >> 10;
                int r = (idx >> 2) & 255;
                int c = idx & 3;
                dst = sdst + mat * A_MAT + (r * SA + c * 8) * 2;
                src = (mat ? Al : Ah) + (size_t)(bm + r) * K + kc + c * 8;
            } else {
                int j = idx - 2048;
                int mat = j >> 9;
                int r = (j >> 2) & 127;
                int c = j & 3;
                dst = sdst + 2 * A_MAT + mat * B_MAT + (r * SA + c * 8) * 2;
                src = (mat ? Bl : Bh) + (size_t)(bn + r) * K + kc + c * 8;
            }
            cp_async16(dst, src);
        }
        CP_COMMIT();
    };

    float acc[4][8][4];
#pragma unroll
    for (int a = 0; a < 4; a++)
#pragma unroll
        for (int b = 0; b < 8; b++)
#pragma unroll
            for (int c = 0; c < 4; c++) acc[a][b][c] = 0.f;

    const int nk = K / 32;
    issue_stage(0, 0);
    issue_stage(1, 32);

    const int a_r = warp_m * 64 + (lane & 15);
    const int a_c8 = lane >> 4;
    const int b_r = warp_n * 64 + (lane & 7) + (lane >> 4) * 8;
    const int b_c8 = (lane >> 3) & 1;

    int sidx = 0;
    for (int kb = 0; kb < nk; kb++) {
        CP_WAIT(1);
        __syncthreads();

        const uint32_t st = sbase + sidx * STAGE2;
        const uint32_t sAh = st;
        const uint32_t sAl = st + A_MAT;
        const uint32_t sBh = st + 2 * A_MAT;
        const uint32_t sBl = st + 2 * A_MAT + B_MAT;

#pragma unroll
        for (int ks = 0; ks < 2; ks++) {
            uint32_t ahi[4][4], alo[4][4];
#pragma unroll
            for (int tm = 0; tm < 4; tm++) {
                uint32_t off = ((a_r + tm * 16) * SA + (ks * 2 + a_c8) * 8) * 2;
                ldsm_x4(ahi[tm], sAh + off);
                ldsm_x4(alo[tm], sAl + off);
            }
#pragma unroll
            for (int g = 0; g < 4; g++) {
                uint32_t bhi[4], blo[4];
                uint32_t off = ((g * 16 + b_r) * SA + (ks * 2 + b_c8) * 8) * 2;
                ldsm_x4(bhi, sBh + off);
                ldsm_x4(blo, sBl + off);
                // pass 1: hi*hi over all 8 acc tiles of this g
#pragma unroll
                for (int tm = 0; tm < 4; tm++)
#pragma unroll
                    for (int sub = 0; sub < 2; sub++)
                        mma_bf16(acc[tm][g * 2 + sub], ahi[tm], bhi + sub * 2);
                // pass 2: hi*lo
#pragma unroll
                for (int tm = 0; tm < 4; tm++)
#pragma unroll
                    for (int sub = 0; sub < 2; sub++)
                        mma_bf16(acc[tm][g * 2 + sub], ahi[tm], blo + sub * 2);
                // pass 3: lo*hi
#pragma unroll
                for (int tm = 0; tm < 4; tm++)
#pragma unroll
                    for (int sub = 0; sub < 2; sub++)
                        mma_bf16(acc[tm][g * 2 + sub], alo[tm], bhi + sub * 2);
            }
        }
        __syncthreads();
        if (kb + 2 < nk) issue_stage((kb + 2) % 3, (kb + 2) * 32);
        sidx = (sidx + 1) == 3 ? 0 : sidx + 1;
    }

    const int crow = lane >> 2;
    const int ccol = (lane & 3) * 2;
#pragma unroll
    for (int tm = 0; tm < 4; tm++) {
#pragma unroll
        for (int t = 0; t < 8; t++) {
            int row = bm + warp_m * 64 + tm * 16 + crow;
            int col = bn + warp_n * 64 + t * 8 + ccol;
            float* p0 = C + (size_t)row * Ntot + col;
            float* p1 = C + (size_t)(row + 8) * Ntot + col;
            p0[0] = acc[tm][t][0]; p0[1] = acc[tm][t][1];
            p1[0] = acc[tm][t][2]; p1[1] = acc[tm][t][3];
        }
    }
}

// ============================================================================
// RMSNorm + RoPE + scatter -> bf16 hi/lo q,k,v
// ============================================================================
__global__ void __launch_bounds__(128) norm_rope_scatter(
    const float* __restrict__ qkv, const float* __restrict__ qg,
    const float* __restrict__ kgm, const float* __restrict__ freqs)
{
    const int blk = blockIdx.x;
    const int h = blk & (HN - 1);
    const int m = blk >> 4;
    const int d = threadIdx.x;
    const int lane = d & 31;
    const int wid = d >> 5;

    const float* base = qkv + (size_t)m * E3;
    float qv = base[h * HDIM + d];
    float kv = base[HN * HDIM + h * HDIM + d];
    float vv = base[2 * HN * HDIM + h * HDIM + d];

    float sq = qv * qv, sk = kv * kv;
#pragma unroll
    for (int off = 16; off > 0; off >>= 1) {
        sq += __shfl_xor_sync(0xffffffffu, sq, off);
        sk += __shfl_xor_sync(0xffffffffu, sk, off);
    }
    __shared__ float red[8];
    if (lane == 0) { red[wid] = sq; red[4 + wid] = sk; }
    __syncthreads();
    if (d < 2) {
        float s = red[d * 4] + red[d * 4 + 1] + red[d * 4 + 2] + red[d * 4 + 3];
        red[d * 4] = rsqrtf(s * (1.0f / HDIM) + EPSV);
    }
    __syncthreads();
    float qr = qv * red[0] * qg[d] * QSCALE;
    float kr = kv * red[4] * kgm[d];

    const int i = d >> 1;
    const float c = freqs[((size_t)m * 64 + i) * 2 + 0];
    const float s = freqs[((size_t)m * 64 + i) * 2 + 1];
    float qo = __shfl_xor_sync(0xffffffffu, qr, 1);
    float ko = __shfl_xor_sync(0xffffffffu, kr, 1);
    float qout, kout;
    if (d & 1) { qout = qo * s + qr * c;  kout = ko * s + kr * c; }
    else       { qout = qr * c - qo * s;  kout = kr * c - ko * s; }

    const int b = m / NN, n = m - b * NN;
    const size_t dst = (((size_t)b * HN + h) * NN + n) * HDIM + d;
    __nv_bfloat16 qh = __float2bfloat16(qout);
    __nv_bfloat16 kh = __float2bfloat16(kout);
    __nv_bfloat16 vh = __float2bfloat16(vv);
    g_qhi[dst] = qh; g_qlo[dst] = __float2bfloat16(qout - __bfloat162float(qh));
    g_khi[dst] = kh; g_klo[dst] = __float2bfloat16(kout - __bfloat162float(kh));
    g_vhi[dst] = vh; g_vlo[dst] = __float2bfloat16(vv - __bfloat162float(vh));
}

// ============================================================================
// Flash attention, bf16-split mma.sync (unchanged from R4, passing).
// ============================================================================
#define SK 136
#define ATT_MAT (128 * SK * 2)
#define ATT_SMEM (6 * ATT_MAT)

__global__ void __launch_bounds__(256, 1) attn_mma(
    const __nv_bfloat16* __restrict__ Qh, const __nv_bfloat16* __restrict__ Ql,
    const __nv_bfloat16* __restrict__ Kh, const __nv_bfloat16* __restrict__ Kl,
    const __nv_bfloat16* __restrict__ Vh, const __nv_bfloat16* __restrict__ Vl,
    __nv_bfloat16* __restrict__ Ohi, __nv_bfloat16* __restrict__ Olo)
{
    extern __shared__ __align__(128) char smA[];
    const uint32_t sbase = smem_u32(smA);
    const uint32_t sQh = sbase, sQl = sbase + ATT_MAT;
    const uint32_t sKh = sbase + 2 * ATT_MAT, sKl = sbase + 3 * ATT_MAT;
    const uint32_t sVh = sbase + 4 * ATT_MAT, sVl = sbase + 5 * ATT_MAT;

    const int tid = threadIdx.x;
    const int lane = tid & 31;
    const int wid = tid >> 5;
    const int qt = blockIdx.x & 15;
    const int bh = blockIdx.x >> 4;

    const size_t seqbase = (size_t)bh * NN * HDIM;
    const __nv_bfloat16* qh_p = Qh + seqbase + (size_t)qt * 128 * HDIM;
    const __nv_bfloat16* ql_p = Ql + seqbase + (size_t)qt * 128 * HDIM;

    {
#pragma unroll
        for (int t = 0; t < 8; t++) {
            int idx = tid + t * 256;
            int row = idx >> 4, c8 = idx & 15;
            uint32_t off = (row * SK + c8 * 8) * 2;
            cp_async16(sQh + off, qh_p + row * HDIM + c8 * 8);
            cp_async16(sQl + off, ql_p + row * HDIM + c8 * 8);
        }
        CP_COMMIT();
    }

    float o[16][4];
#pragma unroll
    for (int t = 0; t < 16; t++)
#pragma unroll
        for (int j = 0; j < 4; j++) o[t][j] = 0.f;
    float mrow0 = -1e30f, mrow1 = -1e30f, lrow0 = 0.f, lrow1 = 0.f;

    const int a_r = wid * 16 + (lane & 15);
    const int a_c8 = lane >> 4;
    const int kb_r = (lane & 7) + (lane >> 4) * 8;
    const int kb_c8 = (lane >> 3) & 1;
    const int v_r = lane & 15;
    const int v_c8 = lane >> 4;

    for (int t0 = 0; t0 < NN; t0 += 128) {
        const __nv_bfloat16* kh_p = Kh + seqbase + (size_t)t0 * HDIM;
        const __nv_bfloat16* kl_p = Kl + seqbase + (size_t)t0 * HDIM;
        const __nv_bfloat16* vh_p = Vh + seqbase + (size_t)t0 * HDIM;
        const __nv_bfloat16* vl_p = Vl + seqbase + (size_t)t0 * HDIM;
#pragma unroll
        for (int t = 0; t < 8; t++) {
            int idx = tid + t * 256;
            int row = idx >> 4, c8 = idx & 15;
            uint32_t off = (row * SK + c8 * 8) * 2;
            int go = row * HDIM + c8 * 8;
            cp_async16(sKh + off, kh_p + go);
            cp_async16(sKl + off, kl_p + go);
            cp_async16(sVh + off, vh_p + go);
            cp_async16(sVl + off, vl_p + go);
        }
        CP_COMMIT();
        CP_WAIT(0);
        __syncthreads();

        float s[16][4];
#pragma unroll
        for (int t = 0; t < 16; t++)
#pragma unroll
            for (int j = 0; j < 4; j++) s[t][j] = 0.f;

#pragma unroll
        for (int kk = 0; kk < 8; kk++) {
            uint32_t qa[4], qb[4];
            uint32_t aoff = (a_r * SK + kk * 16 + a_c8 * 8) * 2;
            ldsm_x4(qa, sQh + aoff);
            ldsm_x4(qb, sQl + aoff);
#pragma unroll
            for (int nt = 0; nt < 8; nt++) {
                uint32_t kf[4], kg2[4];
                uint32_t boff = ((nt * 16 + kb_r) * SK + kk * 16 + kb_c8 * 8) * 2;
                ldsm_x4(kf, sKh + boff);
                ldsm_x4(kg2, sKl + boff);
                mma_bf16(s[2 * nt], qa, kf);
                mma_bf16(s[2 * nt], qa, kg2);
                mma_bf16(s[2 * nt], qb, kf);
                mma_bf16(s[2 * nt + 1], qa, kf + 2);
                mma_bf16(s[2 * nt + 1], qa, kg2 + 2);
                mma_bf16(s[2 * nt + 1], qb, kf + 2);
            }
        }

        float tm0 = -1e30f, tm1 = -1e30f;
#pragma unroll
        for (int t = 0; t < 16; t++) {
            tm0 = fmaxf(tm0, fmaxf(s[t][0], s[t][1]));
            tm1 = fmaxf(tm1, fmaxf(s[t][2], s[t][3]));
        }
        tm0 = fmaxf(tm0, __shfl_xor_sync(0xffffffffu, tm0, 1));
        tm0 = fmaxf(tm0, __shfl_xor_sync(0xffffffffu, tm0, 2));
        tm1 = fmaxf(tm1, __shfl_xor_sync(0xffffffffu, tm1, 1));
        tm1 = fmaxf(tm1, __shfl_xor_sync(0xffffffffu, tm1, 2));
        float mn0 = fmaxf(mrow0, tm0), mn1 = fmaxf(mrow1, tm1);
        float fac0 = __expf(mrow0 - mn0), fac1 = __expf(mrow1 - mn1);
        mrow0 = mn0; mrow1 = mn1;

        float ts0 = 0.f, ts1 = 0.f;
#pragma unroll
        for (int t = 0; t < 16; t++) {
            s[t][0] = __expf(s[t][0] - mn0);
            s[t][1] = __expf(s[t][1] - mn0);
            s[t][2] = __expf(s[t][2] - mn1);
            s[t][3] = __expf(s[t][3] - mn1);
            ts0 += s[t][0] + s[t][1];
            ts1 += s[t][2] + s[t][3];
        }
        ts0 += __shfl_xor_sync(0xffffffffu, ts0, 1);
        ts0 += __shfl_xor_sync(0xffffffffu, ts0, 2);
        ts1 += __shfl_xor_sync(0xffffffffu, ts1, 1);
        ts1 += __shfl_xor_sync(0xffffffffu, ts1, 2);
        lrow0 = lrow0 * fac0 + ts0;
        lrow1 = lrow1 * fac1 + ts1;

#pragma unroll
        for (int t = 0; t < 16; t++) {
            o[t][0] *= fac0; o[t][1] *= fac0;
            o[t][2] *= fac1; o[t][3] *= fac1;
        }

#pragma unroll
        for (int kk = 0; kk < 8; kk++) {
            uint32_t ah[4], al[4];
            split2(s[2 * kk][0],     s[2 * kk][1],     ah[0], al[0]);
            split2(s[2 * kk][2],     s[2 * kk][3],     ah[1], al[1]);
            split2(s[2 * kk + 1][0], s[2 * kk + 1][1], ah[2], al[2]);
            split2(s[2 * kk + 1][2], s[2 * kk + 1][3], ah[3], al[3]);
#pragma unroll
            for (int nt = 0; nt < 8; nt++) {
                uint32_t vf[4], vg[4];
                uint32_t voff = ((kk * 16 + v_r) * SK + nt * 16 + v_c8 * 8) * 2;
                ldsm_x4_t(vf, sVh + voff);
                ldsm_x4_t(vg, sVl + voff);
                mma_bf16(o[2 * nt], ah, vf);
                mma_bf16(o[2 * nt], ah, vg);
                mma_bf16(o[2 * nt], al, vf);
                mma_bf16(o[2 * nt + 1], ah, vf + 2);
                mma_bf16(o[2 * nt + 1], ah, vg + 2);
                mma_bf16(o[2 * nt + 1], al, vf + 2);
            }
        }
        __syncthreads();
    }

    const int b = bh >> 4, h = bh & 15;
    const int n0 = qt * 128 + wid * 16 + (lane >> 2);
    const float inv0 = 1.0f / lrow0, inv1 = 1.0f / lrow1;
    const size_t grow0 = (size_t)(b * NN + n0) * DIMM;
    const size_t grow1 = (size_t)(b * NN + n0 + 8) * DIMM;
#pragma unroll
    for (int t = 0; t < 16; t++) {
        int col = h * HDIM + t * 8 + (lane & 3) * 2;
        uint32_t hi0, lo0, hi1, lo1;
        split2(o[t][0] * inv0, o[t][1] * inv0, hi0, lo0);
        split2(o[t][2] * inv1, o[t][3] * inv1, hi1, lo1);
        *(uint32_t*)(Ohi + grow0 + col) = hi0;
        *(uint32_t*)(Olo + grow0 + col) = lo0;
        *(uint32_t*)(Ohi + grow1 + col) = hi1;
        *(uint32_t*)(Olo + grow1 + col) = lo1;
    }
}

// ============================================================================
// Launch
// ============================================================================
extern "C" void kernel_launch(void* const* d_in, const int* in_sizes, int n_in,
                              void* d_out, int out_size)
{
    const float* x     = (const float*)d_in[0];
    const float* Wqkv  = (const float*)d_in[1];
    const float* qg    = (const float*)d_in[2];
    const float* kg    = (const float*)d_in[3];
    const float* Wout  = (const float*)d_in[4];
    const float* freqs = (const float*)d_in[5];
    float* out = (float*)d_out;

    float* qkv;
    __nv_bfloat16 *qhi, *qlo, *khi, *klo, *vhi, *vlo;
    __nv_bfloat16 *xhi, *xlo, *w1hi, *w1lo, *w2hi, *w2lo, *aohi, *aolo;
    cudaGetSymbolAddress((void**)&qkv, g_qkv);
    cudaGetSymbolAddress((void**)&qhi, g_qhi);
    cudaGetSymbolAddress((void**)&qlo, g_qlo);
    cudaGetSymbolAddress((void**)&khi, g_khi);
    cudaGetSymbolAddress((void**)&klo, g_klo);
    cudaGetSymbolAddress((void**)&vhi, g_vhi);
    cudaGetSymbolAddress((void**)&vlo, g_vlo);
    cudaGetSymbolAddress((void**)&xhi, g_xhi);
    cudaGetSymbolAddress((void**)&xlo, g_xlo);
    cudaGetSymbolAddress((void**)&w1hi, g_w1hi);
    cudaGetSymbolAddress((void**)&w1lo, g_w1lo);
    cudaGetSymbolAddress((void**)&w2hi, g_w2hi);
    cudaGetSymbolAddress((void**)&w2lo, g_w2lo);
    cudaGetSymbolAddress((void**)&aohi, g_aohi);
    cudaGetSymbolAddress((void**)&aolo, g_aolo);

    cudaFuncSetAttribute(gemm_mma_split,
                         cudaFuncAttributeMaxDynamicSharedMemorySize, GEMM_SMEM);
    cudaFuncSetAttribute(attn_mma,
                         cudaFuncAttributeMaxDynamicSharedMemorySize, ATT_SMEM);

    // splits of inputs
    {
        int n4x = (MROWS * DIMM) / 4;
        split_bf16<<<n4x / 256, 256>>>(x, xhi, xlo, n4x);
        int n4w1 = (E3 * DIMM) / 4;
        split_bf16<<<n4w1 / 256, 256>>>(Wqkv, w1hi, w1lo, n4w1);
        int n4w2 = (DIMM * DIMM) / 4;
        split_bf16<<<n4w2 / 256, 256>>>(Wout, w2hi, w2lo, n4w2);
    }
    // 1. QKV GEMM: [4096,2048] x [6144,2048]^T -> [4096,6144]
    {
        dim3 grid(E3 / 128, MROWS / 256);
        gemm_mma_split<<<grid, 256, GEMM_SMEM>>>(xhi, xlo, w1hi, w1lo, qkv, E3, DIMM);
    }
    // 2. RMSNorm + RoPE + scatter (emits bf16 hi/lo q,k,v)
    norm_rope_scatter<<<MROWS * HN, 128>>>(qkv, qg, kg, freqs);
    // 3. Attention (emits bf16 hi/lo attention output)
    attn_mma<<<BB * HN * 16, 256, ATT_SMEM>>>(qhi, qlo, khi, klo, vhi, vlo,
                                              aohi, aolo);
    // 4. out GEMM: [4096,2048] x [2048,2048]^T -> [4096,2048]
    {
        dim3 grid(DIMM / 128, MROWS / 256);
        gemm_mma_split<<<grid, 256, GEMM_SMEM>>>(aohi, aolo, w2hi, w2lo, out, DIMM, DIMM);
    }
}

// round 6
// speedup vs baseline: 1.0676x; 1.0676x over previous
#include <cuda_runtime.h>
#include <cuda_bf16.h>
#include <cstdint>

// Problem constants
#define DIMM   2048
#define HN     16
#define HDIM   128
#define BB     2
#define NN     2048
#define E3     (3 * HN * HDIM)      // 6144
#define MROWS  (BB * NN)            // 4096
#define EPSV   1e-5f
#define QSCALE 0.08838834764831845f // 1/sqrt(128)

// ---------------- scratch (static device arrays; no allocation) -------------
__device__ float g_qkv[(size_t)MROWS * E3];

__device__ __nv_bfloat16 g_qhi[(size_t)BB * HN * NN * HDIM];
__device__ __nv_bfloat16 g_qlo[(size_t)BB * HN * NN * HDIM];
__device__ __nv_bfloat16 g_khi[(size_t)BB * HN * NN * HDIM];
__device__ __nv_bfloat16 g_klo[(size_t)BB * HN * NN * HDIM];
__device__ __nv_bfloat16 g_vhi[(size_t)BB * HN * NN * HDIM];
__device__ __nv_bfloat16 g_vlo[(size_t)BB * HN * NN * HDIM];

__device__ __nv_bfloat16 g_xhi[(size_t)MROWS * DIMM];
__device__ __nv_bfloat16 g_xlo[(size_t)MROWS * DIMM];
__device__ __nv_bfloat16 g_w1hi[(size_t)E3 * DIMM];
__device__ __nv_bfloat16 g_w1lo[(size_t)E3 * DIMM];
__device__ __nv_bfloat16 g_w2hi[(size_t)DIMM * DIMM];
__device__ __nv_bfloat16 g_w2lo[(size_t)DIMM * DIMM];
__device__ __nv_bfloat16 g_aohi[(size_t)MROWS * DIMM];
__device__ __nv_bfloat16 g_aolo[(size_t)MROWS * DIMM];

// ============================================================================
// helpers
// ============================================================================
__device__ __forceinline__ uint32_t smem_u32(const void* p) {
    uint32_t a;
    asm("{ .reg .u64 t; cvta.to.shared.u64 t, %1; cvt.u32.u64 %0, t; }"
        : "=r"(a) : "l"(p));
    return a;
}
__device__ __forceinline__ void cp_async16(uint32_t dst, const void* src) {
    asm volatile("cp.async.cg.shared.global [%0], [%1], 16;"
                 :: "r"(dst), "l"(src));
}
#define CP_COMMIT() asm volatile("cp.async.commit_group;" ::: "memory")
#define CP_WAIT(n)  asm volatile("cp.async.wait_group %0;" :: "n"(n) : "memory")

__device__ __forceinline__ void ldsm_x4(uint32_t* r, uint32_t addr) {
    asm volatile("ldmatrix.sync.aligned.m8n8.x4.shared.b16 {%0,%1,%2,%3}, [%4];"
                 : "=r"(r[0]), "=r"(r[1]), "=r"(r[2]), "=r"(r[3]) : "r"(addr));
}
__device__ __forceinline__ void ldsm_x4_t(uint32_t* r, uint32_t addr) {
    asm volatile("ldmatrix.sync.aligned.m8n8.x4.trans.shared.b16 {%0,%1,%2,%3}, [%4];"
                 : "=r"(r[0]), "=r"(r[1]), "=r"(r[2]), "=r"(r[3]) : "r"(addr));
}
__device__ __forceinline__ void mma_bf16(float* c, const uint32_t* a,
                                         const uint32_t* b) {
    asm volatile(
        "mma.sync.aligned.m16n8k16.row.col.f32.bf16.bf16.f32 "
        "{%0,%1,%2,%3}, {%4,%5,%6,%7}, {%8,%9}, {%0,%1,%2,%3};"
        : "+f"(c[0]), "+f"(c[1]), "+f"(c[2]), "+f"(c[3])
        : "r"(a[0]), "r"(a[1]), "r"(a[2]), "r"(a[3]), "r"(b[0]), "r"(b[1]));
}
__device__ __forceinline__ void split2(float x, float y, uint32_t& hi, uint32_t& lo) {
    __nv_bfloat16 hx = __float2bfloat16(x), hy = __float2bfloat16(y);
    float rx = x - __bfloat162float(hx), ry = y - __bfloat162float(hy);
    __nv_bfloat162 H; H.x = hx; H.y = hy;
    __nv_bfloat162 L; L.x = __float2bfloat16(rx); L.y = __float2bfloat16(ry);
    hi = *(uint32_t*)&H;
    lo = *(uint32_t*)&L;
}

// ============================================================================
// fp32 -> bf16 hi/lo split
// ============================================================================
__global__ void __launch_bounds__(256) split_bf16(
    const float* __restrict__ in, __nv_bfloat16* __restrict__ hi,
    __nv_bfloat16* __restrict__ lo, int n4)
{
    int i = blockIdx.x * 256 + threadIdx.x;
    if (i >= n4) return;
    float4 v = ((const float4*)in)[i];
    union { __nv_bfloat16 b[4]; uint2 u; } H, L;
    float vv[4] = {v.x, v.y, v.z, v.w};
#pragma unroll
    for (int j = 0; j < 4; j++) {
        __nv_bfloat16 h = __float2bfloat16(vv[j]);
        H.b[j] = h;
        L.b[j] = __float2bfloat16(vv[j] - __bfloat162float(h));
    }
    ((uint2*)hi)[i] = H.u;
    ((uint2*)lo)[i] = L.u;
}

// ============================================================================
// bf16 split GEMM (R4 config: CTA 128x128, BK=32, 8 warps 4x2, warp 32x64,
// 2-stage cp.async) with pass-reordered mma: each split pass sweeps the 4
// independent accumulators before the next pass -> no back-to-back RAW.
// ============================================================================
#define SA 40
#define MAT_BYTES (128 * SA * 2)
#define STAGE_BYTES (4 * MAT_BYTES)
#define GEMM_SMEM (2 * STAGE_BYTES)

__global__ void __launch_bounds__(256, 2) gemm_mma_split(
    const __nv_bfloat16* __restrict__ Ah, const __nv_bfloat16* __restrict__ Al,
    const __nv_bfloat16* __restrict__ Bh, const __nv_bfloat16* __restrict__ Bl,
    float* __restrict__ C, int Ntot, int K)
{
    extern __shared__ __align__(128) char sm[];
    const uint32_t sbase = smem_u32(sm);
    const int tid = threadIdx.x;
    const int lane = tid & 31;
    const int wid = tid >> 5;
    const int warp_m = wid & 3;
    const int warp_n = wid >> 2;
    const int bm = blockIdx.y * 128;
    const int bn = blockIdx.x * 128;

    const __nv_bfloat16* srcs[4] = {Ah, Al, Bh, Bl};
    const int rowbase[4] = {bm, bm, bn, bn};

    auto issue_stage = [&](int stage, int kc) {
        uint32_t sdst = sbase + stage * STAGE_BYTES;
#pragma unroll
        for (int t = 0; t < 8; t++) {
            int idx = tid + t * 256;
            int mat = idx >> 9;
            int row = (idx >> 2) & 127;
            int c = idx & 3;
            uint32_t dst = sdst + mat * MAT_BYTES + (row * SA + c * 8) * 2;
            const __nv_bfloat16* src =
                srcs[mat] + (size_t)(rowbase[mat] + row) * K + kc + c * 8;
            cp_async16(dst, src);
        }
        CP_COMMIT();
    };

    float acc[2][8][4];
#pragma unroll
    for (int a = 0; a < 2; a++)
#pragma unroll
        for (int b = 0; b < 8; b++)
#pragma unroll
            for (int c = 0; c < 4; c++) acc[a][b][c] = 0.f;

    const int nk = K / 32;
    issue_stage(0, 0);

    const int a_r = warp_m * 32 + (lane & 15);
    const int a_c8 = lane >> 4;
    const int b_r = warp_n * 64 + (lane & 7) + (lane >> 4) * 8;
    const int b_c8 = (lane >> 3) & 1;

    for (int kb = 0; kb < nk; kb++) {
        if (kb < nk - 1) {
            issue_stage((kb + 1) & 1, (kb + 1) * 32);
            CP_WAIT(1);
        } else {
            CP_WAIT(0);
        }
        __syncthreads();

        const uint32_t st = sbase + (kb & 1) * STAGE_BYTES;
        const uint32_t sAh = st;
        const uint32_t sAl = st + MAT_BYTES;
        const uint32_t sBh = st + 2 * MAT_BYTES;
        const uint32_t sBl = st + 3 * MAT_BYTES;

#pragma unroll
        for (int ks = 0; ks < 2; ks++) {
            uint32_t ahi[2][4], alo[2][4];
#pragma unroll
            for (int tm = 0; tm < 2; tm++) {
                uint32_t off = ((a_r + tm * 16) * SA + (ks * 2 + a_c8) * 8) * 2;
                ldsm_x4(ahi[tm], sAh + off);
                ldsm_x4(alo[tm], sAl + off);
            }
#pragma unroll
            for (int g = 0; g < 4; g++) {
                uint32_t bhi[4], blo[4];
                uint32_t off = ((b_r + g * 16) * SA + (ks * 2 + b_c8) * 8) * 2;
                ldsm_x4(bhi, sBh + off);
                ldsm_x4(blo, sBl + off);
                // pass 1: hi*hi across the 4 independent accumulators
#pragma unroll
                for (int tm = 0; tm < 2; tm++)
#pragma unroll
                    for (int sub = 0; sub < 2; sub++)
                        mma_bf16(acc[tm][g * 2 + sub], ahi[tm], bhi + sub * 2);
                // pass 2: hi*lo
#pragma unroll
                for (int tm = 0; tm < 2; tm++)
#pragma unroll
                    for (int sub = 0; sub < 2; sub++)
                        mma_bf16(acc[tm][g * 2 + sub], ahi[tm], blo + sub * 2);
                // pass 3: lo*hi
#pragma unroll
                for (int tm = 0; tm < 2; tm++)
#pragma unroll
                    for (int sub = 0; sub < 2; sub++)
                        mma_bf16(acc[tm][g * 2 + sub], alo[tm], bhi + sub * 2);
            }
        }
        __syncthreads();
    }

    const int crow = lane >> 2;
    const int ccol = (lane & 3) * 2;
#pragma unroll
    for (int tm = 0; tm < 2; tm++) {
#pragma unroll
        for (int t = 0; t < 8; t++) {
            int row = bm + warp_m * 32 + tm * 16 + crow;
            int col = bn + warp_n * 64 + t * 8 + ccol;
            float* p0 = C + (size_t)row * Ntot + col;
            float* p1 = C + (size_t)(row + 8) * Ntot + col;
            p0[0] = acc[tm][t][0]; p0[1] = acc[tm][t][1];
            p1[0] = acc[tm][t][2]; p1[1] = acc[tm][t][3];
        }
    }
}

// ============================================================================
// RMSNorm + RoPE + scatter -> bf16 hi/lo q,k,v
// ============================================================================
__global__ void __launch_bounds__(128) norm_rope_scatter(
    const float* __restrict__ qkv, const float* __restrict__ qg,
    const float* __restrict__ kgm, const float* __restrict__ freqs)
{
    const int blk = blockIdx.x;
    const int h = blk & (HN - 1);
    const int m = blk >> 4;
    const int d = threadIdx.x;
    const int lane = d & 31;
    const int wid = d >> 5;

    const float* base = qkv + (size_t)m * E3;
    float qv = base[h * HDIM + d];
    float kv = base[HN * HDIM + h * HDIM + d];
    float vv = base[2 * HN * HDIM + h * HDIM + d];

    float sq = qv * qv, sk = kv * kv;
#pragma unroll
    for (int off = 16; off > 0; off >>= 1) {
        sq += __shfl_xor_sync(0xffffffffu, sq, off);
        sk += __shfl_xor_sync(0xffffffffu, sk, off);
    }
    __shared__ float red[8];
    if (lane == 0) { red[wid] = sq; red[4 + wid] = sk; }
    __syncthreads();
    if (d < 2) {
        float s = red[d * 4] + red[d * 4 + 1] + red[d * 4 + 2] + red[d * 4 + 3];
        red[d * 4] = rsqrtf(s * (1.0f / HDIM) + EPSV);
    }
    __syncthreads();
    float qr = qv * red[0] * qg[d] * QSCALE;
    float kr = kv * red[4] * kgm[d];

    const int i = d >> 1;
    const float c = freqs[((size_t)m * 64 + i) * 2 + 0];
    const float s = freqs[((size_t)m * 64 + i) * 2 + 1];
    float qo = __shfl_xor_sync(0xffffffffu, qr, 1);
    float ko = __shfl_xor_sync(0xffffffffu, kr, 1);
    float qout, kout;
    if (d & 1) { qout = qo * s + qr * c;  kout = ko * s + kr * c; }
    else       { qout = qr * c - qo * s;  kout = kr * c - ko * s; }

    const int b = m / NN, n = m - b * NN;
    const size_t dst = (((size_t)b * HN + h) * NN + n) * HDIM + d;
    __nv_bfloat16 qh = __float2bfloat16(qout);
    __nv_bfloat16 kh = __float2bfloat16(kout);
    __nv_bfloat16 vh = __float2bfloat16(vv);
    g_qhi[dst] = qh; g_qlo[dst] = __float2bfloat16(qout - __bfloat162float(qh));
    g_khi[dst] = kh; g_klo[dst] = __float2bfloat16(kout - __bfloat162float(kh));
    g_vhi[dst] = vh; g_vlo[dst] = __float2bfloat16(vv - __bfloat162float(vh));
}

// ============================================================================
// Flash attention, bf16-split mma.sync (unchanged from R4, passing).
// ============================================================================
#define SK 136
#define ATT_MAT (128 * SK * 2)
#define ATT_SMEM (6 * ATT_MAT)

__global__ void __launch_bounds__(256, 1) attn_mma(
    const __nv_bfloat16* __restrict__ Qh, const __nv_bfloat16* __restrict__ Ql,
    const __nv_bfloat16* __restrict__ Kh, const __nv_bfloat16* __restrict__ Kl,
    const __nv_bfloat16* __restrict__ Vh, const __nv_bfloat16* __restrict__ Vl,
    __nv_bfloat16* __restrict__ Ohi, __nv_bfloat16* __restrict__ Olo)
{
    extern __shared__ __align__(128) char smA[];
    const uint32_t sbase = smem_u32(smA);
    const uint32_t sQh = sbase, sQl = sbase + ATT_MAT;
    const uint32_t sKh = sbase + 2 * ATT_MAT, sKl = sbase + 3 * ATT_MAT;
    const uint32_t sVh = sbase + 4 * ATT_MAT, sVl = sbase + 5 * ATT_MAT;

    const int tid = threadIdx.x;
    const int lane = tid & 31;
    const int wid = tid >> 5;
    const int qt = blockIdx.x & 15;
    const int bh = blockIdx.x >> 4;

    const size_t seqbase = (size_t)bh * NN * HDIM;
    const __nv_bfloat16* qh_p = Qh + seqbase + (size_t)qt * 128 * HDIM;
    const __nv_bfloat16* ql_p = Ql + seqbase + (size_t)qt * 128 * HDIM;

    {
#pragma unroll
        for (int t = 0; t < 8; t++) {
            int idx = tid + t * 256;
            int row = idx >> 4, c8 = idx & 15;
            uint32_t off = (row * SK + c8 * 8) * 2;
            cp_async16(sQh + off, qh_p + row * HDIM + c8 * 8);
            cp_async16(sQl + off, ql_p + row * HDIM + c8 * 8);
        }
        CP_COMMIT();
    }

    float o[16][4];
#pragma unroll
    for (int t = 0; t < 16; t++)
#pragma unroll
        for (int j = 0; j < 4; j++) o[t][j] = 0.f;
    float mrow0 = -1e30f, mrow1 = -1e30f, lrow0 = 0.f, lrow1 = 0.f;

    const int a_r = wid * 16 + (lane & 15);
    const int a_c8 = lane >> 4;
    const int kb_r = (lane & 7) + (lane >> 4) * 8;
    const int kb_c8 = (lane >> 3) & 1;
    const int v_r = lane & 15;
    const int v_c8 = lane >> 4;

    for (int t0 = 0; t0 < NN; t0 += 128) {
        const __nv_bfloat16* kh_p = Kh + seqbase + (size_t)t0 * HDIM;
        const __nv_bfloat16* kl_p = Kl + seqbase + (size_t)t0 * HDIM;
        const __nv_bfloat16* vh_p = Vh + seqbase + (size_t)t0 * HDIM;
        const __nv_bfloat16* vl_p = Vl + seqbase + (size_t)t0 * HDIM;
#pragma unroll
        for (int t = 0; t < 8; t++) {
            int idx = tid + t * 256;
            int row = idx >> 4, c8 = idx & 15;
            uint32_t off = (row * SK + c8 * 8) * 2;
            int go = row * HDIM + c8 * 8;
            cp_async16(sKh + off, kh_p + go);
            cp_async16(sKl + off, kl_p + go);
            cp_async16(sVh + off, vh_p + go);
            cp_async16(sVl + off, vl_p + go);
        }
        CP_COMMIT();
        CP_WAIT(0);
        __syncthreads();

        float s[16][4];
#pragma unroll
        for (int t = 0; t < 16; t++)
#pragma unroll
            for (int j = 0; j < 4; j++) s[t][j] = 0.f;

#pragma unroll
        for (int kk = 0; kk < 8; kk++) {
            uint32_t qa[4], qb[4];
            uint32_t aoff = (a_r * SK + kk * 16 + a_c8 * 8) * 2;
            ldsm_x4(qa, sQh + aoff);
            ldsm_x4(qb, sQl + aoff);
#pragma unroll
            for (int nt = 0; nt < 8; nt++) {
                uint32_t kf[4], kg2[4];
                uint32_t boff = ((nt * 16 + kb_r) * SK + kk * 16 + kb_c8 * 8) * 2;
                ldsm_x4(kf, sKh + boff);
                ldsm_x4(kg2, sKl + boff);
                mma_bf16(s[2 * nt], qa, kf);
                mma_bf16(s[2 * nt], qa, kg2);
                mma_bf16(s[2 * nt], qb, kf);
                mma_bf16(s[2 * nt + 1], qa, kf + 2);
                mma_bf16(s[2 * nt + 1], qa, kg2 + 2);
                mma_bf16(s[2 * nt + 1], qb, kf + 2);
            }
        }

        float tm0 = -1e30f, tm1 = -1e30f;
#pragma unroll
        for (int t = 0; t < 16; t++) {
            tm0 = fmaxf(tm0, fmaxf(s[t][0], s[t][1]));
            tm1 = fmaxf(tm1, fmaxf(s[t][2], s[t][3]));
        }
        tm0 = fmaxf(tm0, __shfl_xor_sync(0xffffffffu, tm0, 1));
        tm0 = fmaxf(tm0, __shfl_xor_sync(0xffffffffu, tm0, 2));
        tm1 = fmaxf(tm1, __shfl_xor_sync(0xffffffffu, tm1, 1));
        tm1 = fmaxf(tm1, __shfl_xor_sync(0xffffffffu, tm1, 2));
        float mn0 = fmaxf(mrow0, tm0), mn1 = fmaxf(mrow1, tm1);
        float fac0 = __expf(mrow0 - mn0), fac1 = __expf(mrow1 - mn1);
        mrow0 = mn0; mrow1 = mn1;

        float ts0 = 0.f, ts1 = 0.f;
#pragma unroll
        for (int t = 0; t < 16; t++) {
            s[t][0] = __expf(s[t][0] - mn0);
            s[t][1] = __expf(s[t][1] - mn0);
            s[t][2] = __expf(s[t][2] - mn1);
            s[t][3] = __expf(s[t][3] - mn1);
            ts0 += s[t][0] + s[t][1];
            ts1 += s[t][2] + s[t][3];
        }
        ts0 += __shfl_xor_sync(0xffffffffu, ts0, 1);
        ts0 += __shfl_xor_sync(0xffffffffu, ts0, 2);
        ts1 += __shfl_xor_sync(0xffffffffu, ts1, 1);
        ts1 += __shfl_xor_sync(0xffffffffu, ts1, 2);
        lrow0 = lrow0 * fac0 + ts0;
        lrow1 = lrow1 * fac1 + ts1;

#pragma unroll
        for (int t = 0; t < 16; t++) {
            o[t][0] *= fac0; o[t][1] *= fac0;
            o[t][2] *= fac1; o[t][3] *= fac1;
        }

#pragma unroll
        for (int kk = 0; kk < 8; kk++) {
            uint32_t ah[4], al[4];
            split2(s[2 * kk][0],     s[2 * kk][1],     ah[0], al[0]);
            split2(s[2 * kk][2],     s[2 * kk][3],     ah[1], al[1]);
            split2(s[2 * kk + 1][0], s[2 * kk + 1][1], ah[2], al[2]);
            split2(s[2 * kk + 1][2], s[2 * kk + 1][3], ah[3], al[3]);
#pragma unroll
            for (int nt = 0; nt < 8; nt++) {
                uint32_t vf[4], vg[4];
                uint32_t voff = ((kk * 16 + v_r) * SK + nt * 16 + v_c8 * 8) * 2;
                ldsm_x4_t(vf, sVh + voff);
                ldsm_x4_t(vg, sVl + voff);
                mma_bf16(o[2 * nt], ah, vf);
                mma_bf16(o[2 * nt], ah, vg);
                mma_bf16(o[2 * nt], al, vf);
                mma_bf16(o[2 * nt + 1], ah, vf + 2);
                mma_bf16(o[2 * nt + 1], ah, vg + 2);
                mma_bf16(o[2 * nt + 1], al, vf + 2);
            }
        }
        __syncthreads();
    }

    const int b = bh >> 4, h = bh & 15;
    const int n0 = qt * 128 + wid * 16 + (lane >> 2);
    const float inv0 = 1.0f / lrow0, inv1 = 1.0f / lrow1;
    const size_t grow0 = (size_t)(b * NN + n0) * DIMM;
    const size_t grow1 = (size_t)(b * NN + n0 + 8) * DIMM;
#pragma unroll
    for (int t = 0; t < 16; t++) {
        int col = h * HDIM + t * 8 + (lane & 3) * 2;
        uint32_t hi0, lo0, hi1, lo1;
        split2(o[t][0] * inv0, o[t][1] * inv0, hi0, lo0);
        split2(o[t][2] * inv1, o[t][3] * inv1, hi1, lo1);
        *(uint32_t*)(Ohi + grow0 + col) = hi0;
        *(uint32_t*)(Olo + grow0 + col) = lo0;
        *(uint32_t*)(Ohi + grow1 + col) = hi1;
        *(uint32_t*)(Olo + grow1 + col) = lo1;
    }
}

// ============================================================================
// Launch
// ============================================================================
extern "C" void kernel_launch(void* const* d_in, const int* in_sizes, int n_in,
                              void* d_out, int out_size)
{
    const float* x     = (const float*)d_in[0];
    const float* Wqkv  = (const float*)d_in[1];
    const float* qg    = (const float*)d_in[2];
    const float* kg    = (const float*)d_in[3];
    const float* Wout  = (const float*)d_in[4];
    const float* freqs = (const float*)d_in[5];
    float* out = (float*)d_out;

    float* qkv;
    __nv_bfloat16 *qhi, *qlo, *khi, *klo, *vhi, *vlo;
    __nv_bfloat16 *xhi, *xlo, *w1hi, *w1lo, *w2hi, *w2lo, *aohi, *aolo;
    cudaGetSymbolAddress((void**)&qkv, g_qkv);
    cudaGetSymbolAddress((void**)&qhi, g_qhi);
    cudaGetSymbolAddress((void**)&qlo, g_qlo);
    cudaGetSymbolAddress((void**)&khi, g_khi);
    cudaGetSymbolAddress((void**)&klo, g_klo);
    cudaGetSymbolAddress((void**)&vhi, g_vhi);
    cudaGetSymbolAddress((void**)&vlo, g_vlo);
    cudaGetSymbolAddress((void**)&xhi, g_xhi);
    cudaGetSymbolAddress((void**)&xlo, g_xlo);
    cudaGetSymbolAddress((void**)&w1hi, g_w1hi);
    cudaGetSymbolAddress((void**)&w1lo, g_w1lo);
    cudaGetSymbolAddress((void**)&w2hi, g_w2hi);
    cudaGetSymbolAddress((void**)&w2lo, g_w2lo);
    cudaGetSymbolAddress((void**)&aohi, g_aohi);
    cudaGetSymbolAddress((void**)&aolo, g_aolo);

    cudaFuncSetAttribute(gemm_mma_split,
                         cudaFuncAttributeMaxDynamicSharedMemorySize, GEMM_SMEM);
    cudaFuncSetAttribute(attn_mma,
                         cudaFuncAttributeMaxDynamicSharedMemorySize, ATT_SMEM);

    // splits of inputs
    {
        int n4x = (MROWS * DIMM) / 4;
        split_bf16<<<n4x / 256, 256>>>(x, xhi, xlo, n4x);
        int n4w1 = (E3 * DIMM) / 4;
        split_bf16<<<n4w1 / 256, 256>>>(Wqkv, w1hi, w1lo, n4w1);
        int n4w2 = (DIMM * DIMM) / 4;
        split_bf16<<<n4w2 / 256, 256>>>(Wout, w2hi, w2lo, n4w2);
    }
    // 1. QKV GEMM: [4096,2048] x [6144,2048]^T -> [4096,6144]
    {
        dim3 grid(E3 / 128, MROWS / 128);
        gemm_mma_split<<<grid, 256, GEMM_SMEM>>>(xhi, xlo, w1hi, w1lo, qkv, E3, DIMM);
    }
    // 2. RMSNorm + RoPE + scatter (emits bf16 hi/lo q,k,v)
    norm_rope_scatter<<<MROWS * HN, 128>>>(qkv, qg, kg, freqs);
    // 3. Attention (emits bf16 hi/lo attention output)
    attn_mma<<<BB * HN * 16, 256, ATT_SMEM>>>(qhi, qlo, khi, klo, vhi, vlo,
                                              aohi, aolo);
    // 4. out GEMM: [4096,2048] x [2048,2048]^T -> [4096,2048]
    {
        dim3 grid(DIMM / 128, MROWS / 128);
        gemm_mma_split<<<grid, 256, GEMM_SMEM>>>(aohi, aolo, w2hi, w2lo, out, DIMM, DIMM);
    }
}

// round 7
// speedup vs baseline: 1.0698x; 1.0021x over previous
#include <cuda_runtime.h>
#include <cuda_bf16.h>
#include <cstdint>

// Problem constants
#define DIMM   2048
#define HN     16
#define HDIM   128
#define BB     2
#define NN     2048
#define E3     (3 * HN * HDIM)      // 6144
#define MROWS  (BB * NN)            // 4096
#define EPSV   1e-5f
#define QSCALE 0.08838834764831845f // 1/sqrt(128)

// ---------------- scratch (static device arrays; no allocation) -------------
__device__ float g_qkv[(size_t)MROWS * E3];

__device__ __nv_bfloat16 g_qhi[(size_t)BB * HN * NN * HDIM];
__device__ __nv_bfloat16 g_qlo[(size_t)BB * HN * NN * HDIM];
__device__ __nv_bfloat16 g_khi[(size_t)BB * HN * NN * HDIM];
__device__ __nv_bfloat16 g_klo[(size_t)BB * HN * NN * HDIM];
__device__ __nv_bfloat16 g_vhi[(size_t)BB * HN * NN * HDIM];
__device__ __nv_bfloat16 g_vlo[(size_t)BB * HN * NN * HDIM];

__device__ __nv_bfloat16 g_xhi[(size_t)MROWS * DIMM];
__device__ __nv_bfloat16 g_xlo[(size_t)MROWS * DIMM];
__device__ __nv_bfloat16 g_w1hi[(size_t)E3 * DIMM];
__device__ __nv_bfloat16 g_w1lo[(size_t)E3 * DIMM];
__device__ __nv_bfloat16 g_w2hi[(size_t)DIMM * DIMM];
__device__ __nv_bfloat16 g_w2lo[(size_t)DIMM * DIMM];
__device__ __nv_bfloat16 g_aohi[(size_t)MROWS * DIMM];
__device__ __nv_bfloat16 g_aolo[(size_t)MROWS * DIMM];

// ============================================================================
// helpers
// ============================================================================
__device__ __forceinline__ uint32_t smem_u32(const void* p) {
    uint32_t a;
    asm("{ .reg .u64 t; cvta.to.shared.u64 t, %1; cvt.u32.u64 %0, t; }"
        : "=r"(a) : "l"(p));
    return a;
}
__device__ __forceinline__ void cp_async16(uint32_t dst, const void* src) {
    asm volatile("cp.async.cg.shared.global [%0], [%1], 16;"
                 :: "r"(dst), "l"(src));
}
#define CP_COMMIT() asm volatile("cp.async.commit_group;" ::: "memory")
#define CP_WAIT(n)  asm volatile("cp.async.wait_group %0;" :: "n"(n) : "memory")

__device__ __forceinline__ void ldsm_x4(uint32_t* r, uint32_t addr) {
    asm volatile("ldmatrix.sync.aligned.m8n8.x4.shared.b16 {%0,%1,%2,%3}, [%4];"
                 : "=r"(r[0]), "=r"(r[1]), "=r"(r[2]), "=r"(r[3]) : "r"(addr));
}
__device__ __forceinline__ void ldsm_x4_t(uint32_t* r, uint32_t addr) {
    asm volatile("ldmatrix.sync.aligned.m8n8.x4.trans.shared.b16 {%0,%1,%2,%3}, [%4];"
                 : "=r"(r[0]), "=r"(r[1]), "=r"(r[2]), "=r"(r[3]) : "r"(addr));
}
__device__ __forceinline__ void mma_bf16(float* c, const uint32_t* a,
                                         const uint32_t* b) {
    asm volatile(
        "mma.sync.aligned.m16n8k16.row.col.f32.bf16.bf16.f32 "
        "{%0,%1,%2,%3}, {%4,%5,%6,%7}, {%8,%9}, {%0,%1,%2,%3};"
        : "+f"(c[0]), "+f"(c[1]), "+f"(c[2]), "+f"(c[3])
        : "r"(a[0]), "r"(a[1]), "r"(a[2]), "r"(a[3]), "r"(b[0]), "r"(b[1]));
}
__device__ __forceinline__ void split2(float x, float y, uint32_t& hi, uint32_t& lo) {
    __nv_bfloat16 hx = __float2bfloat16(x), hy = __float2bfloat16(y);
    float rx = x - __bfloat162float(hx), ry = y - __bfloat162float(hy);
    __nv_bfloat162 H; H.x = hx; H.y = hy;
    __nv_bfloat162 L; L.x = __float2bfloat16(rx); L.y = __float2bfloat16(ry);
    hi = *(uint32_t*)&H;
    lo = *(uint32_t*)&L;
}

// ============================================================================
// fp32 -> bf16 hi/lo split
// ============================================================================
__global__ void __launch_bounds__(256) split_bf16(
    const float* __restrict__ in, __nv_bfloat16* __restrict__ hi,
    __nv_bfloat16* __restrict__ lo, int n4)
{
    int i = blockIdx.x * 256 + threadIdx.x;
    if (i >= n4) return;
    float4 v = ((const float4*)in)[i];
    union { __nv_bfloat16 b[4]; uint2 u; } H, L;
    float vv[4] = {v.x, v.y, v.z, v.w};
#pragma unroll
    for (int j = 0; j < 4; j++) {
        __nv_bfloat16 h = __float2bfloat16(vv[j]);
        H.b[j] = h;
        L.b[j] = __float2bfloat16(vv[j] - __bfloat162float(h));
    }
    ((uint2*)hi)[i] = H.u;
    ((uint2*)lo)[i] = L.u;
}

// ============================================================================
// bf16 split GEMM (R4 config: CTA 128x128, BK=32, 8 warps 4x2, warp 32x64,
// 2-stage cp.async) with pass-reordered mma: each split pass sweeps the 4
// independent accumulators before the next pass -> no back-to-back RAW.
// ============================================================================
#define SA 40
#define MAT_BYTES (128 * SA * 2)
#define STAGE_BYTES (4 * MAT_BYTES)
#define GEMM_SMEM (2 * STAGE_BYTES)

__global__ void __launch_bounds__(256, 2) gemm_mma_split(
    const __nv_bfloat16* __restrict__ Ah, const __nv_bfloat16* __restrict__ Al,
    const __nv_bfloat16* __restrict__ Bh, const __nv_bfloat16* __restrict__ Bl,
    float* __restrict__ C, int Ntot, int K)
{
    extern __shared__ __align__(128) char sm[];
    const uint32_t sbase = smem_u32(sm);
    const int tid = threadIdx.x;
    const int lane = tid & 31;
    const int wid = tid >> 5;
    const int warp_m = wid & 3;
    const int warp_n = wid >> 2;
    const int bm = blockIdx.y * 128;
    const int bn = blockIdx.x * 128;

    const __nv_bfloat16* srcs[4] = {Ah, Al, Bh, Bl};
    const int rowbase[4] = {bm, bm, bn, bn};

    auto issue_stage = [&](int stage, int kc) {
        uint32_t sdst = sbase + stage * STAGE_BYTES;
#pragma unroll
        for (int t = 0; t < 8; t++) {
            int idx = tid + t * 256;
            int mat = idx >> 9;
            int row = (idx >> 2) & 127;
            int c = idx & 3;
            uint32_t dst = sdst + mat * MAT_BYTES + (row * SA + c * 8) * 2;
            const __nv_bfloat16* src =
                srcs[mat] + (size_t)(rowbase[mat] + row) * K + kc + c * 8;
            cp_async16(dst, src);
        }
        CP_COMMIT();
    };

    float acc[2][8][4];
#pragma unroll
    for (int a = 0; a < 2; a++)
#pragma unroll
        for (int b = 0; b < 8; b++)
#pragma unroll
            for (int c = 0; c < 4; c++) acc[a][b][c] = 0.f;

    const int nk = K / 32;
    issue_stage(0, 0);

    const int a_r = warp_m * 32 + (lane & 15);
    const int a_c8 = lane >> 4;
    const int b_r = warp_n * 64 + (lane & 7) + (lane >> 4) * 8;
    const int b_c8 = (lane >> 3) & 1;

    for (int kb = 0; kb < nk; kb++) {
        if (kb < nk - 1) {
            issue_stage((kb + 1) & 1, (kb + 1) * 32);
            CP_WAIT(1);
        } else {
            CP_WAIT(0);
        }
        __syncthreads();

        const uint32_t st = sbase + (kb & 1) * STAGE_BYTES;
        const uint32_t sAh = st;
        const uint32_t sAl = st + MAT_BYTES;
        const uint32_t sBh = st + 2 * MAT_BYTES;
        const uint32_t sBl = st + 3 * MAT_BYTES;

#pragma unroll
        for (int ks = 0; ks < 2; ks++) {
            uint32_t ahi[2][4], alo[2][4];
#pragma unroll
            for (int tm = 0; tm < 2; tm++) {
                uint32_t off = ((a_r + tm * 16) * SA + (ks * 2 + a_c8) * 8) * 2;
                ldsm_x4(ahi[tm], sAh + off);
                ldsm_x4(alo[tm], sAl + off);
            }
#pragma unroll
            for (int g = 0; g < 4; g++) {
                uint32_t bhi[4], blo[4];
                uint32_t off = ((b_r + g * 16) * SA + (ks * 2 + b_c8) * 8) * 2;
                ldsm_x4(bhi, sBh + off);
                ldsm_x4(blo, sBl + off);
                // pass 1: hi*hi across the 4 independent accumulators
#pragma unroll
                for (int tm = 0; tm < 2; tm++)
#pragma unroll
                    for (int sub = 0; sub < 2; sub++)
                        mma_bf16(acc[tm][g * 2 + sub], ahi[tm], bhi + sub * 2);
                // pass 2: hi*lo
#pragma unroll
                for (int tm = 0; tm < 2; tm++)
#pragma unroll
                    for (int sub = 0; sub < 2; sub++)
                        mma_bf16(acc[tm][g * 2 + sub], ahi[tm], blo + sub * 2);
                // pass 3: lo*hi
#pragma unroll
                for (int tm = 0; tm < 2; tm++)
#pragma unroll
                    for (int sub = 0; sub < 2; sub++)
                        mma_bf16(acc[tm][g * 2 + sub], alo[tm], bhi + sub * 2);
            }
        }
        __syncthreads();
    }

    const int crow = lane >> 2;
    const int ccol = (lane & 3) * 2;
#pragma unroll
    for (int tm = 0; tm < 2; tm++) {
#pragma unroll
        for (int t = 0; t < 8; t++) {
            int row = bm + warp_m * 32 + tm * 16 + crow;
            int col = bn + warp_n * 64 + t * 8 + ccol;
            float* p0 = C + (size_t)row * Ntot + col;
            float* p1 = C + (size_t)(row + 8) * Ntot + col;
            p0[0] = acc[tm][t][0]; p0[1] = acc[tm][t][1];
            p1[0] = acc[tm][t][2]; p1[1] = acc[tm][t][3];
        }
    }
}

// ============================================================================
// RMSNorm + RoPE + scatter -> bf16 hi/lo q,k,v
// ============================================================================
__global__ void __launch_bounds__(128) norm_rope_scatter(
    const float* __restrict__ qkv, const float* __restrict__ qg,
    const float* __restrict__ kgm, const float* __restrict__ freqs)
{
    const int blk = blockIdx.x;
    const int h = blk & (HN - 1);
    const int m = blk >> 4;
    const int d = threadIdx.x;
    const int lane = d & 31;
    const int wid = d >> 5;

    const float* base = qkv + (size_t)m * E3;
    float qv = base[h * HDIM + d];
    float kv = base[HN * HDIM + h * HDIM + d];
    float vv = base[2 * HN * HDIM + h * HDIM + d];

    float sq = qv * qv, sk = kv * kv;
#pragma unroll
    for (int off = 16; off > 0; off >>= 1) {
        sq += __shfl_xor_sync(0xffffffffu, sq, off);
        sk += __shfl_xor_sync(0xffffffffu, sk, off);
    }
    __shared__ float red[8];
    if (lane == 0) { red[wid] = sq; red[4 + wid] = sk; }
    __syncthreads();
    if (d < 2) {
        float s = red[d * 4] + red[d * 4 + 1] + red[d * 4 + 2] + red[d * 4 + 3];
        red[d * 4] = rsqrtf(s * (1.0f / HDIM) + EPSV);
    }
    __syncthreads();
    float qr = qv * red[0] * qg[d] * QSCALE;
    float kr = kv * red[4] * kgm[d];

    const int i = d >> 1;
    const float c = freqs[((size_t)m * 64 + i) * 2 + 0];
    const float s = freqs[((size_t)m * 64 + i) * 2 + 1];
    float qo = __shfl_xor_sync(0xffffffffu, qr, 1);
    float ko = __shfl_xor_sync(0xffffffffu, kr, 1);
    float qout, kout;
    if (d & 1) { qout = qo * s + qr * c;  kout = ko * s + kr * c; }
    else       { qout = qr * c - qo * s;  kout = kr * c - ko * s; }

    const int b = m / NN, n = m - b * NN;
    const size_t dst = (((size_t)b * HN + h) * NN + n) * HDIM + d;
    __nv_bfloat16 qh = __float2bfloat16(qout);
    __nv_bfloat16 kh = __float2bfloat16(kout);
    __nv_bfloat16 vh = __float2bfloat16(vv);
    g_qhi[dst] = qh; g_qlo[dst] = __float2bfloat16(qout - __bfloat162float(qh));
    g_khi[dst] = kh; g_klo[dst] = __float2bfloat16(kout - __bfloat162float(kh));
    g_vhi[dst] = vh; g_vlo[dst] = __float2bfloat16(vv - __bfloat162float(vh));
}

// ============================================================================
// Flash attention, bf16-split mma.sync (unchanged from R4, passing).
// ============================================================================
#define SK 136
#define ATT_MAT (128 * SK * 2)
#define ATT_SMEM (6 * ATT_MAT)

__global__ void __launch_bounds__(256, 1) attn_mma(
    const __nv_bfloat16* __restrict__ Qh, const __nv_bfloat16* __restrict__ Ql,
    const __nv_bfloat16* __restrict__ Kh, const __nv_bfloat16* __restrict__ Kl,
    const __nv_bfloat16* __restrict__ Vh, const __nv_bfloat16* __restrict__ Vl,
    __nv_bfloat16* __restrict__ Ohi, __nv_bfloat16* __restrict__ Olo)
{
    extern __shared__ __align__(128) char smA[];
    const uint32_t sbase = smem_u32(smA);
    const uint32_t sQh = sbase, sQl = sbase + ATT_MAT;
    const uint32_t sKh = sbase + 2 * ATT_MAT, sKl = sbase + 3 * ATT_MAT;
    const uint32_t sVh = sbase + 4 * ATT_MAT, sVl = sbase + 5 * ATT_MAT;

    const int tid = threadIdx.x;
    const int lane = tid & 31;
    const int wid = tid >> 5;
    const int qt = blockIdx.x & 15;
    const int bh = blockIdx.x >> 4;

    const size_t seqbase = (size_t)bh * NN * HDIM;
    const __nv_bfloat16* qh_p = Qh + seqbase + (size_t)qt * 128 * HDIM;
    const __nv_bfloat16* ql_p = Ql + seqbase + (size_t)qt * 128 * HDIM;

    {
#pragma unroll
        for (int t = 0; t < 8; t++) {
            int idx = tid + t * 256;
            int row = idx >> 4, c8 = idx & 15;
            uint32_t off = (row * SK + c8 * 8) * 2;
            cp_async16(sQh + off, qh_p + row * HDIM + c8 * 8);
            cp_async16(sQl + off, ql_p + row * HDIM + c8 * 8);
        }
        CP_COMMIT();
    }

    float o[16][4];
#pragma unroll
    for (int t = 0; t < 16; t++)
#pragma unroll
        for (int j = 0; j < 4; j++) o[t][j] = 0.f;
    float mrow0 = -1e30f, mrow1 = -1e30f, lrow0 = 0.f, lrow1 = 0.f;

    const int a_r = wid * 16 + (lane & 15);
    const int a_c8 = lane >> 4;
    const int kb_r = (lane & 7) + (lane >> 4) * 8;
    const int kb_c8 = (lane >> 3) & 1;
    const int v_r = lane & 15;
    const int v_c8 = lane >> 4;

    for (int t0 = 0; t0 < NN; t0 += 128) {
        const __nv_bfloat16* kh_p = Kh + seqbase + (size_t)t0 * HDIM;
        const __nv_bfloat16* kl_p = Kl + seqbase + (size_t)t0 * HDIM;
        const __nv_bfloat16* vh_p = Vh + seqbase + (size_t)t0 * HDIM;
        const __nv_bfloat16* vl_p = Vl + seqbase + (size_t)t0 * HDIM;
#pragma unroll
        for (int t = 0; t < 8; t++) {
            int idx = tid + t * 256;
            int row = idx >> 4, c8 = idx & 15;
            uint32_t off = (row * SK + c8 * 8) * 2;
            int go = row * HDIM + c8 * 8;
            cp_async16(sKh + off, kh_p + go);
            cp_async16(sKl + off, kl_p + go);
            cp_async16(sVh + off, vh_p + go);
            cp_async16(sVl + off, vl_p + go);
        }
        CP_COMMIT();
        CP_WAIT(0);
        __syncthreads();

        float s[16][4];
#pragma unroll
        for (int t = 0; t < 16; t++)
#pragma unroll
            for (int j = 0; j < 4; j++) s[t][j] = 0.f;

#pragma unroll
        for (int kk = 0; kk < 8; kk++) {
            uint32_t qa[4], qb[4];
            uint32_t aoff = (a_r * SK + kk * 16 + a_c8 * 8) * 2;
            ldsm_x4(qa, sQh + aoff);
            ldsm_x4(qb, sQl + aoff);
#pragma unroll
            for (int nt = 0; nt < 8; nt++) {
                uint32_t kf[4], kg2[4];
                uint32_t boff = ((nt * 16 + kb_r) * SK + kk * 16 + kb_c8 * 8) * 2;
                ldsm_x4(kf, sKh + boff);
                ldsm_x4(kg2, sKl + boff);
                mma_bf16(s[2 * nt], qa, kf);
                mma_bf16(s[2 * nt], qa, kg2);
                mma_bf16(s[2 * nt], qb, kf);
                mma_bf16(s[2 * nt + 1], qa, kf + 2);
                mma_bf16(s[2 * nt + 1], qa, kg2 + 2);
                mma_bf16(s[2 * nt + 1], qb, kf + 2);
            }
        }

        float tm0 = -1e30f, tm1 = -1e30f;
#pragma unroll
        for (int t = 0; t < 16; t++) {
            tm0 = fmaxf(tm0, fmaxf(s[t][0], s[t][1]));
            tm1 = fmaxf(tm1, fmaxf(s[t][2], s[t][3]));
        }
        tm0 = fmaxf(tm0, __shfl_xor_sync(0xffffffffu, tm0, 1));
        tm0 = fmaxf(tm0, __shfl_xor_sync(0xffffffffu, tm0, 2));
        tm1 = fmaxf(tm1, __shfl_xor_sync(0xffffffffu, tm1, 1));
        tm1 = fmaxf(tm1, __shfl_xor_sync(0xffffffffu, tm1, 2));
        float mn0 = fmaxf(mrow0, tm0), mn1 = fmaxf(mrow1, tm1);
        float fac0 = __expf(mrow0 - mn0), fac1 = __expf(mrow1 - mn1);
        mrow0 = mn0; mrow1 = mn1;

        float ts0 = 0.f, ts1 = 0.f;
#pragma unroll
        for (int t = 0; t < 16; t++) {
            s[t][0] = __expf(s[t][0] - mn0);
            s[t][1] = __expf(s[t][1] - mn0);
            s[t][2] = __expf(s[t][2] - mn1);
            s[t][3] = __expf(s[t][3] - mn1);
            ts0 += s[t][0] + s[t][1];
            ts1 += s[t][2] + s[t][3];
        }
        ts0 += __shfl_xor_sync(0xffffffffu, ts0, 1);
        ts0 += __shfl_xor_sync(0xffffffffu, ts0, 2);
        ts1 += __shfl_xor_sync(0xffffffffu, ts1, 1);
        ts1 += __shfl_xor_sync(0xffffffffu, ts1, 2);
        lrow0 = lrow0 * fac0 + ts0;
        lrow1 = lrow1 * fac1 + ts1;

#pragma unroll
        for (int t = 0; t < 16; t++) {
            o[t][0] *= fac0; o[t][1] *= fac0;
            o[t][2] *= fac1; o[t][3] *= fac1;
        }

#pragma unroll
        for (int kk = 0; kk < 8; kk++) {
            uint32_t ah[4], al[4];
            split2(s[2 * kk][0],     s[2 * kk][1],     ah[0], al[0]);
            split2(s[2 * kk][2],     s[2 * kk][3],     ah[1], al[1]);
            split2(s[2 * kk + 1][0], s[2 * kk + 1][1], ah[2], al[2]);
            split2(s[2 * kk + 1][2], s[2 * kk + 1][3], ah[3], al[3]);
#pragma unroll
            for (int nt = 0; nt < 8; nt++) {
                uint32_t vf[4], vg[4];
                uint32_t voff = ((kk * 16 + v_r) * SK + nt * 16 + v_c8 * 8) * 2;
                ldsm_x4_t(vf, sVh + voff);
                ldsm_x4_t(vg, sVl + voff);
                mma_bf16(o[2 * nt], ah, vf);
                mma_bf16(o[2 * nt], ah, vg);
                mma_bf16(o[2 * nt], al, vf);
                mma_bf16(o[2 * nt + 1], ah, vf + 2);
                mma_bf16(o[2 * nt + 1], ah, vg + 2);
                mma_bf16(o[2 * nt + 1], al, vf + 2);
            }
        }
        __syncthreads();
    }

    const int b = bh >> 4, h = bh & 15;
    const int n0 = qt * 128 + wid * 16 + (lane >> 2);
    const float inv0 = 1.0f / lrow0, inv1 = 1.0f / lrow1;
    const size_t grow0 = (size_t)(b * NN + n0) * DIMM;
    const size_t grow1 = (size_t)(b * NN + n0 + 8) * DIMM;
#pragma unroll
    for (int t = 0; t < 16; t++) {
        int col = h * HDIM + t * 8 + (lane & 3) * 2;
        uint32_t hi0, lo0, hi1, lo1;
        split2(o[t][0] * inv0, o[t][1] * inv0, hi0, lo0);
        split2(o[t][2] * inv1, o[t][3] * inv1, hi1, lo1);
        *(uint32_t*)(Ohi + grow0 + col) = hi0;
        *(uint32_t*)(Olo + grow0 + col) = lo0;
        *(uint32_t*)(Ohi + grow1 + col) = hi1;
        *(uint32_t*)(Olo + grow1 + col) = lo1;
    }
}

// ============================================================================
// Launch
// ============================================================================
extern "C" void kernel_launch(void* const* d_in, const int* in_sizes, int n_in,
                              void* d_out, int out_size)
{
    const float* x     = (const float*)d_in[0];
    const float* Wqkv  = (const float*)d_in[1];
    const float* qg    = (const float*)d_in[2];
    const float* kg    = (const float*)d_in[3];
    const float* Wout  = (const float*)d_in[4];
    const float* freqs = (const float*)d_in[5];
    float* out = (float*)d_out;

    float* qkv;
    __nv_bfloat16 *qhi, *qlo, *khi, *klo, *vhi, *vlo;
    __nv_bfloat16 *xhi, *xlo, *w1hi, *w1lo, *w2hi, *w2lo, *aohi, *aolo;
    cudaGetSymbolAddress((void**)&qkv, g_qkv);
    cudaGetSymbolAddress((void**)&qhi, g_qhi);
    cudaGetSymbolAddress((void**)&qlo, g_qlo);
    cudaGetSymbolAddress((void**)&khi, g_khi);
    cudaGetSymbolAddress((void**)&klo, g_klo);
    cudaGetSymbolAddress((void**)&vhi, g_vhi);
    cudaGetSymbolAddress((void**)&vlo, g_vlo);
    cudaGetSymbolAddress((void**)&xhi, g_xhi);
    cudaGetSymbolAddress((void**)&xlo, g_xlo);
    cudaGetSymbolAddress((void**)&w1hi, g_w1hi);
    cudaGetSymbolAddress((void**)&w1lo, g_w1lo);
    cudaGetSymbolAddress((void**)&w2hi, g_w2hi);
    cudaGetSymbolAddress((void**)&w2lo, g_w2lo);
    cudaGetSymbolAddress((void**)&aohi, g_aohi);
    cudaGetSymbolAddress((void**)&aolo, g_aolo);

    cudaFuncSetAttribute(gemm_mma_split,
                         cudaFuncAttributeMaxDynamicSharedMemorySize, GEMM_SMEM);
    cudaFuncSetAttribute(attn_mma,
                         cudaFuncAttributeMaxDynamicSharedMemorySize, ATT_SMEM);

    // splits of inputs
    {
        int n4x = (MROWS * DIMM) / 4;
        split_bf16<<<n4x / 256, 256>>>(x, xhi, xlo, n4x);
        int n4w1 = (E3 * DIMM) / 4;
        split_bf16<<<n4w1 / 256, 256>>>(Wqkv, w1hi, w1lo, n4w1);
        int n4w2 = (DIMM * DIMM) / 4;
        split_bf16<<<n4w2 / 256, 256>>>(Wout, w2hi, w2lo, n4w2);
    }
    // 1. QKV GEMM: [4096,2048] x [6144,2048]^T -> [4096,6144]
    {
        dim3 grid(E3 / 128, MROWS / 128);
        gemm_mma_split<<<grid, 256, GEMM_SMEM>>>(xhi, xlo, w1hi, w1lo, qkv, E3, DIMM);
    }
    // 2. RMSNorm + RoPE + scatter (emits bf16 hi/lo q,k,v)
    norm_rope_scatter<<<MROWS * HN, 128>>>(qkv, qg, kg, freqs);
    // 3. Attention (emits bf16 hi/lo attention output)
    attn_mma<<<BB * HN * 16, 256, ATT_SMEM>>>(qhi, qlo, khi, klo, vhi, vlo,
                                              aohi, aolo);
    // 4. out GEMM: [4096,2048] x [2048,2048]^T -> [4096,2048]
    {
        dim3 grid(DIMM / 128, MROWS / 128);
        gemm_mma_split<<<grid, 256, GEMM_SMEM>>>(aohi, aolo, w2hi, w2lo, out, DIMM, DIMM);
    }
}

// round 8
// speedup vs baseline: 1.1122x; 1.0396x over previous
#include <cuda_runtime.h>
#include <cuda_bf16.h>
#include <cuda_fp16.h>
#include <cstdint>

// Problem constants
#define DIMM   2048
#define HN     16
#define HDIM   128
#define BB     2
#define NN     2048
#define E3     (3 * HN * HDIM)      // 6144
#define MROWS  (BB * NN)            // 4096
#define EPSV   1e-5f
#define QSCALE 0.08838834764831845f // 1/sqrt(128)
#define LOG2E  1.4426950408889634f

// ---------------- scratch (static device arrays; no allocation) -------------
__device__ float g_qkv[(size_t)MROWS * E3];

__device__ __nv_bfloat16 g_qhi[(size_t)BB * HN * NN * HDIM];
__device__ __nv_bfloat16 g_qlo[(size_t)BB * HN * NN * HDIM];
__device__ __nv_bfloat16 g_khi[(size_t)BB * HN * NN * HDIM];
__device__ __nv_bfloat16 g_klo[(size_t)BB * HN * NN * HDIM];
__device__ __half        g_vhi[(size_t)BB * HN * NN * HDIM];
__device__ __half        g_vlo[(size_t)BB * HN * NN * HDIM];

__device__ __nv_bfloat16 g_xhi[(size_t)MROWS * DIMM];
__device__ __nv_bfloat16 g_xlo[(size_t)MROWS * DIMM];
__device__ __nv_bfloat16 g_w1hi[(size_t)E3 * DIMM];
__device__ __nv_bfloat16 g_w1lo[(size_t)E3 * DIMM];
__device__ __nv_bfloat16 g_w2hi[(size_t)DIMM * DIMM];
__device__ __nv_bfloat16 g_w2lo[(size_t)DIMM * DIMM];
__device__ __nv_bfloat16 g_aohi[(size_t)MROWS * DIMM];
__device__ __nv_bfloat16 g_aolo[(size_t)MROWS * DIMM];

// ============================================================================
// helpers
// ============================================================================
__device__ __forceinline__ uint32_t smem_u32(const void* p) {
    uint32_t a;
    asm("{ .reg .u64 t; cvta.to.shared.u64 t, %1; cvt.u32.u64 %0, t; }"
        : "=r"(a) : "l"(p));
    return a;
}
__device__ __forceinline__ void cp_async16(uint32_t dst, const void* src) {
    asm volatile("cp.async.cg.shared.global [%0], [%1], 16;"
                 :: "r"(dst), "l"(src));
}
#define CP_COMMIT() asm volatile("cp.async.commit_group;" ::: "memory")
#define CP_WAIT(n)  asm volatile("cp.async.wait_group %0;" :: "n"(n) : "memory")

__device__ __forceinline__ void ldsm_x4(uint32_t* r, uint32_t addr) {
    asm volatile("ldmatrix.sync.aligned.m8n8.x4.shared.b16 {%0,%1,%2,%3}, [%4];"
                 : "=r"(r[0]), "=r"(r[1]), "=r"(r[2]), "=r"(r[3]) : "r"(addr));
}
__device__ __forceinline__ void ldsm_x4_t(uint32_t* r, uint32_t addr) {
    asm volatile("ldmatrix.sync.aligned.m8n8.x4.trans.shared.b16 {%0,%1,%2,%3}, [%4];"
                 : "=r"(r[0]), "=r"(r[1]), "=r"(r[2]), "=r"(r[3]) : "r"(addr));
}
__device__ __forceinline__ void mma_bf16(float* c, const uint32_t* a,
                                         const uint32_t* b) {
    asm volatile(
        "mma.sync.aligned.m16n8k16.row.col.f32.bf16.bf16.f32 "
        "{%0,%1,%2,%3}, {%4,%5,%6,%7}, {%8,%9}, {%0,%1,%2,%3};"
        : "+f"(c[0]), "+f"(c[1]), "+f"(c[2]), "+f"(c[3])
        : "r"(a[0]), "r"(a[1]), "r"(a[2]), "r"(a[3]), "r"(b[0]), "r"(b[1]));
}
__device__ __forceinline__ void mma_f16(float* c, const uint32_t* a,
                                        const uint32_t* b) {
    asm volatile(
        "mma.sync.aligned.m16n8k16.row.col.f32.f16.f16.f32 "
        "{%0,%1,%2,%3}, {%4,%5,%6,%7}, {%8,%9}, {%0,%1,%2,%3};"
        : "+f"(c[0]), "+f"(c[1]), "+f"(c[2]), "+f"(c[3])
        : "r"(a[0]), "r"(a[1]), "r"(a[2]), "r"(a[3]), "r"(b[0]), "r"(b[1]));
}
__device__ __forceinline__ void split2(float x, float y, uint32_t& hi, uint32_t& lo) {
    __nv_bfloat16 hx = __float2bfloat16(x), hy = __float2bfloat16(y);
    float rx = x - __bfloat162float(hx), ry = y - __bfloat162float(hy);
    __nv_bfloat162 H; H.x = hx; H.y = hy;
    __nv_bfloat162 L; L.x = __float2bfloat16(rx); L.y = __float2bfloat16(ry);
    hi = *(uint32_t*)&H;
    lo = *(uint32_t*)&L;
}
__device__ __forceinline__ uint32_t packh2(float lo, float hi) {
    uint32_t r;
    asm("cvt.rn.f16x2.f32 %0, %1, %2;" : "=r"(r) : "f"(hi), "f"(lo));
    return r;
}
__device__ __forceinline__ uint32_t h2exp2(uint32_t x) {
    uint32_t d;
    asm("ex2.approx.f16x2 %0, %1;" : "=r"(d) : "r"(x));
    return d;
}

// ============================================================================
// fp32 -> bf16 hi/lo split
// ============================================================================
__global__ void __launch_bounds__(256) split_bf16(
    const float* __restrict__ in, __nv_bfloat16* __restrict__ hi,
    __nv_bfloat16* __restrict__ lo, int n4)
{
    int i = blockIdx.x * 256 + threadIdx.x;
    if (i >= n4) return;
    float4 v = ((const float4*)in)[i];
    union { __nv_bfloat16 b[4]; uint2 u; } H, L;
    float vv[4] = {v.x, v.y, v.z, v.w};
#pragma unroll
    for (int j = 0; j < 4; j++) {
        __nv_bfloat16 h = __float2bfloat16(vv[j]);
        H.b[j] = h;
        L.b[j] = __float2bfloat16(vv[j] - __bfloat162float(h));
    }
    ((uint2*)hi)[i] = H.u;
    ((uint2*)lo)[i] = L.u;
}

// ============================================================================
// bf16 split GEMM (R4 config, passing)
// ============================================================================
#define SA 40
#define MAT_BYTES (128 * SA * 2)
#define STAGE_BYTES (4 * MAT_BYTES)
#define GEMM_SMEM (2 * STAGE_BYTES)

__global__ void __launch_bounds__(256, 2) gemm_mma_split(
    const __nv_bfloat16* __restrict__ Ah, const __nv_bfloat16* __restrict__ Al,
    const __nv_bfloat16* __restrict__ Bh, const __nv_bfloat16* __restrict__ Bl,
    float* __restrict__ C, int Ntot, int K)
{
    extern __shared__ __align__(128) char sm[];
    const uint32_t sbase = smem_u32(sm);
    const int tid = threadIdx.x;
    const int lane = tid & 31;
    const int wid = tid >> 5;
    const int warp_m = wid & 3;
    const int warp_n = wid >> 2;
    const int bm = blockIdx.y * 128;
    const int bn = blockIdx.x * 128;

    const __nv_bfloat16* srcs[4] = {Ah, Al, Bh, Bl};
    const int rowbase[4] = {bm, bm, bn, bn};

    auto issue_stage = [&](int stage, int kc) {
        uint32_t sdst = sbase + stage * STAGE_BYTES;
#pragma unroll
        for (int t = 0; t < 8; t++) {
            int idx = tid + t * 256;
            int mat = idx >> 9;
            int row = (idx >> 2) & 127;
            int c = idx & 3;
            uint32_t dst = sdst + mat * MAT_BYTES + (row * SA + c * 8) * 2;
            const __nv_bfloat16* src =
                srcs[mat] + (size_t)(rowbase[mat] + row) * K + kc + c * 8;
            cp_async16(dst, src);
        }
        CP_COMMIT();
    };

    float acc[2][8][4];
#pragma unroll
    for (int a = 0; a < 2; a++)
#pragma unroll
        for (int b = 0; b < 8; b++)
#pragma unroll
            for (int c = 0; c < 4; c++) acc[a][b][c] = 0.f;

    const int nk = K / 32;
    issue_stage(0, 0);

    const int a_r = warp_m * 32 + (lane & 15);
    const int a_c8 = lane >> 4;
    const int b_r = warp_n * 64 + (lane & 7) + (lane >> 4) * 8;
    const int b_c8 = (lane >> 3) & 1;

    for (int kb = 0; kb < nk; kb++) {
        if (kb < nk - 1) {
            issue_stage((kb + 1) & 1, (kb + 1) * 32);
            CP_WAIT(1);
        } else {
            CP_WAIT(0);
        }
        __syncthreads();

        const uint32_t st = sbase + (kb & 1) * STAGE_BYTES;
        const uint32_t sAh = st;
        const uint32_t sAl = st + MAT_BYTES;
        const uint32_t sBh = st + 2 * MAT_BYTES;
        const uint32_t sBl = st + 3 * MAT_BYTES;

#pragma unroll
        for (int ks = 0; ks < 2; ks++) {
            uint32_t ahi[2][4], alo[2][4];
#pragma unroll
            for (int tm = 0; tm < 2; tm++) {
                uint32_t off = ((a_r + tm * 16) * SA + (ks * 2 + a_c8) * 8) * 2;
                ldsm_x4(ahi[tm], sAh + off);
                ldsm_x4(alo[tm], sAl + off);
            }
#pragma unroll
            for (int g = 0; g < 4; g++) {
                uint32_t bhi[4], blo[4];
                uint32_t off = ((b_r + g * 16) * SA + (ks * 2 + b_c8) * 8) * 2;
                ldsm_x4(bhi, sBh + off);
                ldsm_x4(blo, sBl + off);
#pragma unroll
                for (int tm = 0; tm < 2; tm++)
#pragma unroll
                    for (int sub = 0; sub < 2; sub++)
                        mma_bf16(acc[tm][g * 2 + sub], ahi[tm], bhi + sub * 2);
#pragma unroll
                for (int tm = 0; tm < 2; tm++)
#pragma unroll
                    for (int sub = 0; sub < 2; sub++)
                        mma_bf16(acc[tm][g * 2 + sub], ahi[tm], blo + sub * 2);
#pragma unroll
                for (int tm = 0; tm < 2; tm++)
#pragma unroll
                    for (int sub = 0; sub < 2; sub++)
                        mma_bf16(acc[tm][g * 2 + sub], alo[tm], bhi + sub * 2);
            }
        }
        __syncthreads();
    }

    const int crow = lane >> 2;
    const int ccol = (lane & 3) * 2;
#pragma unroll
    for (int tm = 0; tm < 2; tm++) {
#pragma unroll
        for (int t = 0; t < 8; t++) {
            int row = bm + warp_m * 32 + tm * 16 + crow;
            int col = bn + warp_n * 64 + t * 8 + ccol;
            float* p0 = C + (size_t)row * Ntot + col;
            float* p1 = C + (size_t)(row + 8) * Ntot + col;
            p0[0] = acc[tm][t][0]; p0[1] = acc[tm][t][1];
            p1[0] = acc[tm][t][2]; p1[1] = acc[tm][t][3];
        }
    }
}

// ============================================================================
// RMSNorm + RoPE + scatter -> q,k bf16 hi/lo ; v fp16 hi/lo
// ============================================================================
__global__ void __launch_bounds__(128) norm_rope_scatter(
    const float* __restrict__ qkv, const float* __restrict__ qg,
    const float* __restrict__ kgm, const float* __restrict__ freqs)
{
    const int blk = blockIdx.x;
    const int h = blk & (HN - 1);
    const int m = blk >> 4;
    const int d = threadIdx.x;
    const int lane = d & 31;
    const int wid = d >> 5;

    const float* base = qkv + (size_t)m * E3;
    float qv = base[h * HDIM + d];
    float kv = base[HN * HDIM + h * HDIM + d];
    float vv = base[2 * HN * HDIM + h * HDIM + d];

    float sq = qv * qv, sk = kv * kv;
#pragma unroll
    for (int off = 16; off > 0; off >>= 1) {
        sq += __shfl_xor_sync(0xffffffffu, sq, off);
        sk += __shfl_xor_sync(0xffffffffu, sk, off);
    }
    __shared__ float red[8];
    if (lane == 0) { red[wid] = sq; red[4 + wid] = sk; }
    __syncthreads();
    if (d < 2) {
        float s = red[d * 4] + red[d * 4 + 1] + red[d * 4 + 2] + red[d * 4 + 3];
        red[d * 4] = rsqrtf(s * (1.0f / HDIM) + EPSV);
    }
    __syncthreads();
    float qr = qv * red[0] * qg[d] * QSCALE;
    float kr = kv * red[4] * kgm[d];

    const int i = d >> 1;
    const float c = freqs[((size_t)m * 64 + i) * 2 + 0];
    const float s = freqs[((size_t)m * 64 + i) * 2 + 1];
    float qo = __shfl_xor_sync(0xffffffffu, qr, 1);
    float ko = __shfl_xor_sync(0xffffffffu, kr, 1);
    float qout, kout;
    if (d & 1) { qout = qo * s + qr * c;  kout = ko * s + kr * c; }
    else       { qout = qr * c - qo * s;  kout = kr * c - ko * s; }

    const int b = m / NN, n = m - b * NN;
    const size_t dst = (((size_t)b * HN + h) * NN + n) * HDIM + d;
    __nv_bfloat16 qh = __float2bfloat16(qout);
    __nv_bfloat16 kh = __float2bfloat16(kout);
    __half vh = __float2half_rn(vv);
    g_qhi[dst] = qh; g_qlo[dst] = __float2bfloat16(qout - __bfloat162float(qh));
    g_khi[dst] = kh; g_klo[dst] = __float2bfloat16(kout - __bfloat162float(kh));
    g_vhi[dst] = vh; g_vlo[dst] = __float2half_rn(vv - __half2float(vh));
}

// ============================================================================
// Flash attention: QK bf16 3-pass, softmax via ex2.approx.f16x2 (P fp16
// exact), PV fp16 2-pass, row-sums via P*ones mma.
// ============================================================================
#define SK 136
#define ATT_MAT (128 * SK * 2)
#define ATT_SMEM (6 * ATT_MAT)

__global__ void __launch_bounds__(256, 1) attn_mma(
    const __nv_bfloat16* __restrict__ Qh, const __nv_bfloat16* __restrict__ Ql,
    const __nv_bfloat16* __restrict__ Kh, const __nv_bfloat16* __restrict__ Kl,
    const __half* __restrict__ Vh, const __half* __restrict__ Vl,
    __nv_bfloat16* __restrict__ Ohi, __nv_bfloat16* __restrict__ Olo)
{
    extern __shared__ __align__(128) char smA[];
    const uint32_t sbase = smem_u32(smA);
    const uint32_t sQh = sbase, sQl = sbase + ATT_MAT;
    const uint32_t sKh = sbase + 2 * ATT_MAT, sKl = sbase + 3 * ATT_MAT;
    const uint32_t sVh = sbase + 4 * ATT_MAT, sVl = sbase + 5 * ATT_MAT;

    const int tid = threadIdx.x;
    const int lane = tid & 31;
    const int wid = tid >> 5;
    const int qt = blockIdx.x & 15;
    const int bh = blockIdx.x >> 4;

    const size_t seqbase = (size_t)bh * NN * HDIM;
    const __nv_bfloat16* qh_p = Qh + seqbase + (size_t)qt * 128 * HDIM;
    const __nv_bfloat16* ql_p = Ql + seqbase + (size_t)qt * 128 * HDIM;

    {
#pragma unroll
        for (int t = 0; t < 8; t++) {
            int idx = tid + t * 256;
            int row = idx >> 4, c8 = idx & 15;
            uint32_t off = (row * SK + c8 * 8) * 2;
            cp_async16(sQh + off, qh_p + row * HDIM + c8 * 8);
            cp_async16(sQl + off, ql_p + row * HDIM + c8 * 8);
        }
        CP_COMMIT();
    }

    float o[16][4];
#pragma unroll
    for (int t = 0; t < 16; t++)
#pragma unroll
        for (int j = 0; j < 4; j++) o[t][j] = 0.f;
    float mrow0 = -1e30f, mrow1 = -1e30f, lrow0 = 0.f, lrow1 = 0.f;

    const uint32_t ones2 = 0x3C003C00u;  // (1.0h, 1.0h)
    const uint32_t bones[2] = {ones2, ones2};

    const int a_r = wid * 16 + (lane & 15);
    const int a_c8 = lane >> 4;
    const int kb_r = (lane & 7) + (lane >> 4) * 8;
    const int kb_c8 = (lane >> 3) & 1;
    const int v_r = lane & 15;
    const int v_c8 = lane >> 4;

    for (int t0 = 0; t0 < NN; t0 += 128) {
        const __nv_bfloat16* kh_p = Kh + seqbase + (size_t)t0 * HDIM;
        const __nv_bfloat16* kl_p = Kl + seqbase + (size_t)t0 * HDIM;
        const __half* vh_p = Vh + seqbase + (size_t)t0 * HDIM;
        const __half* vl_p = Vl + seqbase + (size_t)t0 * HDIM;
#pragma unroll
        for (int t = 0; t < 8; t++) {
            int idx = tid + t * 256;
            int row = idx >> 4, c8 = idx & 15;
            uint32_t off = (row * SK + c8 * 8) * 2;
            int go = row * HDIM + c8 * 8;
            cp_async16(sKh + off, kh_p + go);
            cp_async16(sKl + off, kl_p + go);
            cp_async16(sVh + off, vh_p + go);
            cp_async16(sVl + off, vl_p + go);
        }
        CP_COMMIT();
        CP_WAIT(0);
        __syncthreads();

        // ---- S = Q K^T (bf16, 3 passes) ----
        float s[16][4];
#pragma unroll
        for (int t = 0; t < 16; t++)
#pragma unroll
            for (int j = 0; j < 4; j++) s[t][j] = 0.f;

#pragma unroll
        for (int kk = 0; kk < 8; kk++) {
            uint32_t qa[4], qb[4];
            uint32_t aoff = (a_r * SK + kk * 16 + a_c8 * 8) * 2;
            ldsm_x4(qa, sQh + aoff);
            ldsm_x4(qb, sQl + aoff);
#pragma unroll
            for (int nt = 0; nt < 8; nt++) {
                uint32_t kf[4], kg2[4];
                uint32_t boff = ((nt * 16 + kb_r) * SK + kk * 16 + kb_c8 * 8) * 2;
                ldsm_x4(kf, sKh + boff);
                ldsm_x4(kg2, sKl + boff);
                mma_bf16(s[2 * nt], qa, kf);
                mma_bf16(s[2 * nt], qa, kg2);
                mma_bf16(s[2 * nt], qb, kf);
                mma_bf16(s[2 * nt + 1], qa, kf + 2);
                mma_bf16(s[2 * nt + 1], qa, kg2 + 2);
                mma_bf16(s[2 * nt + 1], qb, kf + 2);
            }
        }

        // ---- online softmax: max, then P = exp2((s-mn)*log2e) in fp16 ----
        float tm0 = -1e30f, tm1 = -1e30f;
#pragma unroll
        for (int t = 0; t < 16; t++) {
            tm0 = fmaxf(tm0, fmaxf(s[t][0], s[t][1]));
            tm1 = fmaxf(tm1, fmaxf(s[t][2], s[t][3]));
        }
        tm0 = fmaxf(tm0, __shfl_xor_sync(0xffffffffu, tm0, 1));
        tm0 = fmaxf(tm0, __shfl_xor_sync(0xffffffffu, tm0, 2));
        tm1 = fmaxf(tm1, __shfl_xor_sync(0xffffffffu, tm1, 1));
        tm1 = fmaxf(tm1, __shfl_xor_sync(0xffffffffu, tm1, 2));
        float mn0 = fmaxf(mrow0, tm0), mn1 = fmaxf(mrow1, tm1);
        float fac0 = __expf(mrow0 - mn0), fac1 = __expf(mrow1 - mn1);
        mrow0 = mn0; mrow1 = mn1;

        const float mnl0 = mn0 * LOG2E, mnl1 = mn1 * LOG2E;
        uint32_t ph[16][2];
#pragma unroll
        for (int t = 0; t < 16; t++) {
            float e0 = fmaf(s[t][0], LOG2E, -mnl0);
            float e1 = fmaf(s[t][1], LOG2E, -mnl0);
            float e2 = fmaf(s[t][2], LOG2E, -mnl1);
            float e3 = fmaf(s[t][3], LOG2E, -mnl1);
            ph[t][0] = h2exp2(packh2(e0, e1));
            ph[t][1] = h2exp2(packh2(e2, e3));
        }

        // ---- row sums via P * ones (fp16 mma) ----
        float lacc[4] = {0.f, 0.f, 0.f, 0.f};
#pragma unroll
        for (int kk = 0; kk < 8; kk++) {
            uint32_t ah[4] = {ph[2 * kk][0], ph[2 * kk][1],
                              ph[2 * kk + 1][0], ph[2 * kk + 1][1]};
            mma_f16(lacc, ah, bones);
        }
        lrow0 = lrow0 * fac0 + lacc[0];
        lrow1 = lrow1 * fac1 + lacc[2];

#pragma unroll
        for (int t = 0; t < 16; t++) {
            o[t][0] *= fac0; o[t][1] *= fac0;
            o[t][2] *= fac1; o[t][3] *= fac1;
        }

        // ---- O += P V (fp16, 2 passes) ----
#pragma unroll
        for (int kk = 0; kk < 8; kk++) {
            uint32_t ah[4] = {ph[2 * kk][0], ph[2 * kk][1],
                              ph[2 * kk + 1][0], ph[2 * kk + 1][1]};
#pragma unroll
            for (int nt = 0; nt < 8; nt++) {
                uint32_t vf[4], vg[4];
                uint32_t voff = ((kk * 16 + v_r) * SK + nt * 16 + v_c8 * 8) * 2;
                ldsm_x4_t(vf, sVh + voff);
                ldsm_x4_t(vg, sVl + voff);
                mma_f16(o[2 * nt], ah, vf);
                mma_f16(o[2 * nt], ah, vg);
                mma_f16(o[2 * nt + 1], ah, vf + 2);
                mma_f16(o[2 * nt + 1], ah, vg + 2);
            }
        }
        __syncthreads();
    }

    const int b = bh >> 4, h = bh & 15;
    const int n0 = qt * 128 + wid * 16 + (lane >> 2);
    const float inv0 = 1.0f / lrow0, inv1 = 1.0f / lrow1;
    const size_t grow0 = (size_t)(b * NN + n0) * DIMM;
    const size_t grow1 = (size_t)(b * NN + n0 + 8) * DIMM;
#pragma unroll
    for (int t = 0; t < 16; t++) {
        int col = h * HDIM + t * 8 + (lane & 3) * 2;
        uint32_t hi0, lo0, hi1, lo1;
        split2(o[t][0] * inv0, o[t][1] * inv0, hi0, lo0);
        split2(o[t][2] * inv1, o[t][3] * inv1, hi1, lo1);
        *(uint32_t*)(Ohi + grow0 + col) = hi0;
        *(uint32_t*)(Olo + grow0 + col) = lo0;
        *(uint32_t*)(Ohi + grow1 + col) = hi1;
        *(uint32_t*)(Olo + grow1 + col) = lo1;
    }
}

// ============================================================================
// Launch
// ============================================================================
extern "C" void kernel_launch(void* const* d_in, const int* in_sizes, int n_in,
                              void* d_out, int out_size)
{
    const float* x     = (const float*)d_in[0];
    const float* Wqkv  = (const float*)d_in[1];
    const float* qg    = (const float*)d_in[2];
    const float* kg    = (const float*)d_in[3];
    const float* Wout  = (const float*)d_in[4];
    const float* freqs = (const float*)d_in[5];
    float* out = (float*)d_out;

    float* qkv;
    __nv_bfloat16 *qhi, *qlo, *khi, *klo;
    __half *vhi, *vlo;
    __nv_bfloat16 *xhi, *xlo, *w1hi, *w1lo, *w2hi, *w2lo, *aohi, *aolo;
    cudaGetSymbolAddress((void**)&qkv, g_qkv);
    cudaGetSymbolAddress((void**)&qhi, g_qhi);
    cudaGetSymbolAddress((void**)&qlo, g_qlo);
    cudaGetSymbolAddress((void**)&khi, g_khi);
    cudaGetSymbolAddress((void**)&klo, g_klo);
    cudaGetSymbolAddress((void**)&vhi, g_vhi);
    cudaGetSymbolAddress((void**)&vlo, g_vlo);
    cudaGetSymbolAddress((void**)&xhi, g_xhi);
    cudaGetSymbolAddress((void**)&xlo, g_xlo);
    cudaGetSymbolAddress((void**)&w1hi, g_w1hi);
    cudaGetSymbolAddress((void**)&w1lo, g_w1lo);
    cudaGetSymbolAddress((void**)&w2hi, g_w2hi);
    cudaGetSymbolAddress((void**)&w2lo, g_w2lo);
    cudaGetSymbolAddress((void**)&aohi, g_aohi);
    cudaGetSymbolAddress((void**)&aolo, g_aolo);

    cudaFuncSetAttribute(gemm_mma_split,
                         cudaFuncAttributeMaxDynamicSharedMemorySize, GEMM_SMEM);
    cudaFuncSetAttribute(attn_mma,
                         cudaFuncAttributeMaxDynamicSharedMemorySize, ATT_SMEM);

    // splits of inputs
    {
        int n4x = (MROWS * DIMM) / 4;
        split_bf16<<<n4x / 256, 256>>>(x, xhi, xlo, n4x);
        int n4w1 = (E3 * DIMM) / 4;
        split_bf16<<<n4w1 / 256, 256>>>(Wqkv, w1hi, w1lo, n4w1);
        int n4w2 = (DIMM * DIMM) / 4;
        split_bf16<<<n4w2 / 256, 256>>>(Wout, w2hi, w2lo, n4w2);
    }
    // 1. QKV GEMM
    {
        dim3 grid(E3 / 128, MROWS / 128);
        gemm_mma_split<<<grid, 256, GEMM_SMEM>>>(xhi, xlo, w1hi, w1lo, qkv, E3, DIMM);
    }
    // 2. RMSNorm + RoPE + scatter
    norm_rope_scatter<<<MROWS * HN, 128>>>(qkv, qg, kg, freqs);
    // 3. Attention
    attn_mma<<<BB * HN * 16, 256, ATT_SMEM>>>(qhi, qlo, khi, klo, vhi, vlo,
                                              aohi, aolo);
    // 4. out GEMM
    {
        dim3 grid(DIMM / 128, MROWS / 128);
        gemm_mma_split<<<grid, 256, GEMM_SMEM>>>(aohi, aolo, w2hi, w2lo, out, DIMM, DIMM);
    }
}

// round 11
// speedup vs baseline: 1.2260x; 1.1023x over previous
#include <cuda_runtime.h>
#include <cuda_bf16.h>
#include <cuda_fp16.h>
#include <cstdint>

// Problem constants
#define DIMM   2048
#define HN     16
#define HDIM   128
#define BB     2
#define NN     2048
#define E3     (3 * HN * HDIM)      // 6144
#define MROWS  (BB * NN)            // 4096
#define EPSV   1e-5f
#define QSCALE 0.08838834764831845f // 1/sqrt(128)
#define LOG2E  1.4426950408889634f

// ---------------- scratch (static device arrays; no allocation) -------------
__device__ float g_qkv[(size_t)MROWS * E3];

__device__ __nv_bfloat16 g_qhi[(size_t)BB * HN * NN * HDIM];
__device__ __nv_bfloat16 g_qlo[(size_t)BB * HN * NN * HDIM];
__device__ __nv_bfloat16 g_khi[(size_t)BB * HN * NN * HDIM];
__device__ __nv_bfloat16 g_klo[(size_t)BB * HN * NN * HDIM];
__device__ __half        g_vhi[(size_t)BB * HN * NN * HDIM];
__device__ __half        g_vlo[(size_t)BB * HN * NN * HDIM];

__device__ __nv_bfloat16 g_xhi[(size_t)MROWS * DIMM];
__device__ __nv_bfloat16 g_xlo[(size_t)MROWS * DIMM];
__device__ __nv_bfloat16 g_w1hi[(size_t)E3 * DIMM];
__device__ __nv_bfloat16 g_w1lo[(size_t)E3 * DIMM];
__device__ __nv_bfloat16 g_w2hi[(size_t)DIMM * DIMM];
__device__ __nv_bfloat16 g_w2lo[(size_t)DIMM * DIMM];
__device__ __nv_bfloat16 g_aohi[(size_t)MROWS * DIMM];
__device__ __nv_bfloat16 g_aolo[(size_t)MROWS * DIMM];

// ============================================================================
// helpers
// ============================================================================
__device__ __forceinline__ uint32_t smem_u32(const void* p) {
    uint32_t a;
    asm("{ .reg .u64 t; cvta.to.shared.u64 t, %1; cvt.u32.u64 %0, t; }"
        : "=r"(a) : "l"(p));
    return a;
}
__device__ __forceinline__ void cp_async16(uint32_t dst, const void* src) {
    asm volatile("cp.async.cg.shared.global [%0], [%1], 16;"
                 :: "r"(dst), "l"(src));
}
#define CP_COMMIT() asm volatile("cp.async.commit_group;" ::: "memory")
#define CP_WAIT(n)  asm volatile("cp.async.wait_group %0;" :: "n"(n) : "memory")

__device__ __forceinline__ void ldsm_x4(uint32_t* r, uint32_t addr) {
    asm volatile("ldmatrix.sync.aligned.m8n8.x4.shared.b16 {%0,%1,%2,%3}, [%4];"
                 : "=r"(r[0]), "=r"(r[1]), "=r"(r[2]), "=r"(r[3]) : "r"(addr));
}
__device__ __forceinline__ void ldsm_x4_t(uint32_t* r, uint32_t addr) {
    asm volatile("ldmatrix.sync.aligned.m8n8.x4.trans.shared.b16 {%0,%1,%2,%3}, [%4];"
                 : "=r"(r[0]), "=r"(r[1]), "=r"(r[2]), "=r"(r[3]) : "r"(addr));
}
__device__ __forceinline__ void mma_bf16(float* c, const uint32_t* a,
                                         const uint32_t* b) {
    asm volatile(
        "mma.sync.aligned.m16n8k16.row.col.f32.bf16.bf16.f32 "
        "{%0,%1,%2,%3}, {%4,%5,%6,%7}, {%8,%9}, {%0,%1,%2,%3};"
        : "+f"(c[0]), "+f"(c[1]), "+f"(c[2]), "+f"(c[3])
        : "r"(a[0]), "r"(a[1]), "r"(a[2]), "r"(a[3]), "r"(b[0]), "r"(b[1]));
}
__device__ __forceinline__ void mma_f16(float* c, const uint32_t* a,
                                        const uint32_t* b) {
    asm volatile(
        "mma.sync.aligned.m16n8k16.row.col.f32.f16.f16.f32 "
        "{%0,%1,%2,%3}, {%4,%5,%6,%7}, {%8,%9}, {%0,%1,%2,%3};"
        : "+f"(c[0]), "+f"(c[1]), "+f"(c[2]), "+f"(c[3])
        : "r"(a[0]), "r"(a[1]), "r"(a[2]), "r"(a[3]), "r"(b[0]), "r"(b[1]));
}
__device__ __forceinline__ void split2(float x, float y, uint32_t& hi, uint32_t& lo) {
    __nv_bfloat16 hx = __float2bfloat16(x), hy = __float2bfloat16(y);
    float rx = x - __bfloat162float(hx), ry = y - __bfloat162float(hy);
    __nv_bfloat162 H; H.x = hx; H.y = hy;
    __nv_bfloat162 L; L.x = __float2bfloat16(rx); L.y = __float2bfloat16(ry);
    hi = *(uint32_t*)&H;
    lo = *(uint32_t*)&L;
}
__device__ __forceinline__ uint32_t packh2(float lo, float hi) {
    uint32_t r;
    asm("cvt.rn.f16x2.f32 %0, %1, %2;" : "=r"(r) : "f"(hi), "f"(lo));
    return r;
}
__device__ __forceinline__ uint32_t h2exp2(uint32_t x) {
    uint32_t d;
    asm("ex2.approx.f16x2 %0, %1;" : "=r"(d) : "r"(x));
    return d;
}
// swizzled offset for 64B rows: chunk c in 0..3 (16B units)
__device__ __forceinline__ uint32_t swz64(int row, int c) {
    return (uint32_t)(row * 64 + ((c ^ ((row >> 1) & 3)) << 4));
}

// ============================================================================
// fp32 -> bf16 hi/lo split
// ============================================================================
__global__ void __launch_bounds__(256) split_bf16(
    const float* __restrict__ in, __nv_bfloat16* __restrict__ hi,
    __nv_bfloat16* __restrict__ lo, int n4)
{
    int i = blockIdx.x * 256 + threadIdx.x;
    if (i >= n4) return;
    float4 v = ((const float4*)in)[i];
    union { __nv_bfloat16 b[4]; uint2 u; } H, L;
    float vv[4] = {v.x, v.y, v.z, v.w};
#pragma unroll
    for (int j = 0; j < 4; j++) {
        __nv_bfloat16 h = __float2bfloat16(vv[j]);
        H.b[j] = h;
        L.b[j] = __float2bfloat16(vv[j] - __bfloat162float(h));
    }
    ((uint2*)hi)[i] = H.u;
    ((uint2*)lo)[i] = L.u;
}

// ============================================================================
// bf16 split GEMM: CTA 128x128, BK=32, warp 32x64, 3-stage swizzled smem,
// one __syncthreads per k-iteration.  (under test this round)
// ============================================================================
#define GMAT 8192                       // 128 rows x 64B, swizzled
#define GSTAGE (4 * GMAT)               // Ahi Alo Bhi Blo = 32768
#define GEMM_SMEM (3 * GSTAGE)          // 98304

__global__ void __launch_bounds__(256, 2) gemm_mma_split(
    const __nv_bfloat16* __restrict__ Ah, const __nv_bfloat16* __restrict__ Al,
    const __nv_bfloat16* __restrict__ Bh, const __nv_bfloat16* __restrict__ Bl,
    float* __restrict__ C, int Ntot, int K)
{
    extern __shared__ __align__(128) char sm[];
    const uint32_t sbase = smem_u32(sm);
    const int tid = threadIdx.x;
    const int lane = tid & 31;
    const int wid = tid >> 5;
    const int warp_m = wid & 3;
    const int warp_n = wid >> 2;
    const int bm = blockIdx.y * 128;
    const int bn = blockIdx.x * 128;

    const __nv_bfloat16* srcs[4] = {Ah, Al, Bh, Bl};
    const int rowbase[4] = {bm, bm, bn, bn};

    auto issue_stage = [&](int stage, int kc) {
        uint32_t sdst = sbase + stage * GSTAGE;
#pragma unroll
        for (int t = 0; t < 8; t++) {
            int idx = tid + t * 256;
            int mat = idx >> 9;
            int row = (idx >> 2) & 127;
            int c = idx & 3;
            uint32_t dst = sdst + mat * GMAT + swz64(row, c);
            const __nv_bfloat16* src =
                srcs[mat] + (size_t)(rowbase[mat] + row) * K + kc + c * 8;
            cp_async16(dst, src);
        }
        CP_COMMIT();
    };

    float acc[2][8][4];
#pragma unroll
    for (int a = 0; a < 2; a++)
#pragma unroll
        for (int b = 0; b < 8; b++)
#pragma unroll
            for (int c = 0; c < 4; c++) acc[a][b][c] = 0.f;

    const int nk = K / 32;
    issue_stage(0, 0);
    issue_stage(1, 32);

    const int a_r = warp_m * 32 + (lane & 15);
    const int a_c8 = lane >> 4;
    const int b_r = warp_n * 64 + (lane & 7) + (lane >> 4) * 8;
    const int b_c8 = (lane >> 3) & 1;

    for (int kb = 0; kb < nk; kb++) {
        if (kb < nk - 1) { CP_WAIT(1); } else { CP_WAIT(0); }
        __syncthreads();
        if (kb + 2 < nk) issue_stage((kb + 2) % 3, (kb + 2) * 32);

        const uint32_t st = sbase + (kb % 3) * GSTAGE;
        const uint32_t sAh = st;
        const uint32_t sAl = st + GMAT;
        const uint32_t sBh = st + 2 * GMAT;
        const uint32_t sBl = st + 3 * GMAT;

#pragma unroll
        for (int ks = 0; ks < 2; ks++) {
            uint32_t ahi[2][4], alo[2][4];
#pragma unroll
            for (int tm = 0; tm < 2; tm++) {
                uint32_t off = swz64(a_r + tm * 16, ks * 2 + a_c8);
                ldsm_x4(ahi[tm], sAh + off);
                ldsm_x4(alo[tm], sAl + off);
            }
#pragma unroll
            for (int g = 0; g < 4; g++) {
                uint32_t bhi[4], blo[4];
                uint32_t off = swz64(b_r + g * 16, ks * 2 + b_c8);
                ldsm_x4(bhi, sBh + off);
                ldsm_x4(blo, sBl + off);
#pragma unroll
                for (int tm = 0; tm < 2; tm++)
#pragma unroll
                    for (int sub = 0; sub < 2; sub++)
                        mma_bf16(acc[tm][g * 2 + sub], ahi[tm], bhi + sub * 2);
#pragma unroll
                for (int tm = 0; tm < 2; tm++)
#pragma unroll
                    for (int sub = 0; sub < 2; sub++)
                        mma_bf16(acc[tm][g * 2 + sub], ahi[tm], blo + sub * 2);
#pragma unroll
                for (int tm = 0; tm < 2; tm++)
#pragma unroll
                    for (int sub = 0; sub < 2; sub++)
                        mma_bf16(acc[tm][g * 2 + sub], alo[tm], bhi + sub * 2);
            }
        }
    }

    const int crow = lane >> 2;
    const int ccol = (lane & 3) * 2;
#pragma unroll
    for (int tm = 0; tm < 2; tm++) {
#pragma unroll
        for (int t = 0; t < 8; t++) {
            int row = bm + warp_m * 32 + tm * 16 + crow;
            int col = bn + warp_n * 64 + t * 8 + ccol;
            float* p0 = C + (size_t)row * Ntot + col;
            float* p1 = C + (size_t)(row + 8) * Ntot + col;
            p0[0] = acc[tm][t][0]; p0[1] = acc[tm][t][1];
            p1[0] = acc[tm][t][2]; p1[1] = acc[tm][t][3];
        }
    }
}

// ============================================================================
// RMSNorm + RoPE + scatter -> q,k bf16 hi/lo ; v fp16 hi/lo
// ============================================================================
__global__ void __launch_bounds__(128) norm_rope_scatter(
    const float* __restrict__ qkv, const float* __restrict__ qg,
    const float* __restrict__ kgm, const float* __restrict__ freqs)
{
    const int blk = blockIdx.x;
    const int h = blk & (HN - 1);
    const int m = blk >> 4;
    const int d = threadIdx.x;
    const int lane = d & 31;
    const int wid = d >> 5;

    const float* base = qkv + (size_t)m * E3;
    float qv = base[h * HDIM + d];
    float kv = base[HN * HDIM + h * HDIM + d];
    float vv = base[2 * HN * HDIM + h * HDIM + d];

    float sq = qv * qv, sk = kv * kv;
#pragma unroll
    for (int off = 16; off > 0; off >>= 1) {
        sq += __shfl_xor_sync(0xffffffffu, sq, off);
        sk += __shfl_xor_sync(0xffffffffu, sk, off);
    }
    __shared__ float red[8];
    if (lane == 0) { red[wid] = sq; red[4 + wid] = sk; }
    __syncthreads();
    if (d < 2) {
        float s = red[d * 4] + red[d * 4 + 1] + red[d * 4 + 2] + red[d * 4 + 3];
        red[d * 4] = rsqrtf(s * (1.0f / HDIM) + EPSV);
    }
    __syncthreads();
    float qr = qv * red[0] * qg[d] * QSCALE;
    float kr = kv * red[4] * kgm[d];

    const int i = d >> 1;
    const float c = freqs[((size_t)m * 64 + i) * 2 + 0];
    const float s = freqs[((size_t)m * 64 + i) * 2 + 1];
    float qo = __shfl_xor_sync(0xffffffffu, qr, 1);
    float ko = __shfl_xor_sync(0xffffffffu, kr, 1);
    float qout, kout;
    if (d & 1) { qout = qo * s + qr * c;  kout = ko * s + kr * c; }
    else       { qout = qr * c - qo * s;  kout = kr * c - ko * s; }

    const int b = m / NN, n = m - b * NN;
    const size_t dst = (((size_t)b * HN + h) * NN + n) * HDIM + d;
    __nv_bfloat16 qh = __float2bfloat16(qout);
    __nv_bfloat16 kh = __float2bfloat16(kout);
    __half vh = __float2half_rn(vv);
    g_qhi[dst] = qh; g_qlo[dst] = __float2bfloat16(qout - __bfloat162float(qh));
    g_khi[dst] = kh; g_klo[dst] = __float2bfloat16(kout - __bfloat162float(kh));
    g_vhi[dst] = vh; g_vlo[dst] = __float2half_rn(vv - __half2float(vh));
}

// ============================================================================
// Flash attention (R8 version verbatim — known good): QK bf16 3-pass,
// fp16 ex2 softmax, PV fp16 2-pass, P*ones row sums, CP_WAIT(0) per tile.
// ============================================================================
#define SK 136
#define ATT_MAT (128 * SK * 2)
#define ATT_SMEM (6 * ATT_MAT)

__global__ void __launch_bounds__(256, 1) attn_mma(
    const __nv_bfloat16* __restrict__ Qh, const __nv_bfloat16* __restrict__ Ql,
    const __nv_bfloat16* __restrict__ Kh, const __nv_bfloat16* __restrict__ Kl,
    const __half* __restrict__ Vh, const __half* __restrict__ Vl,
    __nv_bfloat16* __restrict__ Ohi, __nv_bfloat16* __restrict__ Olo)
{
    extern __shared__ __align__(128) char smA[];
    const uint32_t sbase = smem_u32(smA);
    const uint32_t sQh = sbase, sQl = sbase + ATT_MAT;
    const uint32_t sKh = sbase + 2 * ATT_MAT, sKl = sbase + 3 * ATT_MAT;
    const uint32_t sVh = sbase + 4 * ATT_MAT, sVl = sbase + 5 * ATT_MAT;

    const int tid = threadIdx.x;
    const int lane = tid & 31;
    const int wid = tid >> 5;
    const int qt = blockIdx.x & 15;
    const int bh = blockIdx.x >> 4;

    const size_t seqbase = (size_t)bh * NN * HDIM;
    const __nv_bfloat16* qh_p = Qh + seqbase + (size_t)qt * 128 * HDIM;
    const __nv_bfloat16* ql_p = Ql + seqbase + (size_t)qt * 128 * HDIM;

    {
#pragma unroll
        for (int t = 0; t < 8; t++) {
            int idx = tid + t * 256;
            int row = idx >> 4, c8 = idx & 15;
            uint32_t off = (row * SK + c8 * 8) * 2;
            cp_async16(sQh + off, qh_p + row * HDIM + c8 * 8);
            cp_async16(sQl + off, ql_p + row * HDIM + c8 * 8);
        }
        CP_COMMIT();
    }

    float o[16][4];
#pragma unroll
    for (int t = 0; t < 16; t++)
#pragma unroll
        for (int j = 0; j < 4; j++) o[t][j] = 0.f;
    float mrow0 = -1e30f, mrow1 = -1e30f, lrow0 = 0.f, lrow1 = 0.f;

    const uint32_t ones2 = 0x3C003C00u;
    const uint32_t bones[2] = {ones2, ones2};

    const int a_r = wid * 16 + (lane & 15);
    const int a_c8 = lane >> 4;
    const int kb_r = (lane & 7) + (lane >> 4) * 8;
    const int kb_c8 = (lane >> 3) & 1;
    const int v_r = lane & 15;
    const int v_c8 = lane >> 4;

    for (int t0 = 0; t0 < NN; t0 += 128) {
        const __nv_bfloat16* kh_p = Kh + seqbase + (size_t)t0 * HDIM;
        const __nv_bfloat16* kl_p = Kl + seqbase + (size_t)t0 * HDIM;
        const __half* vh_p = Vh + seqbase + (size_t)t0 * HDIM;
        const __half* vl_p = Vl + seqbase + (size_t)t0 * HDIM;
#pragma unroll
        for (int t = 0; t < 8; t++) {
            int idx = tid + t * 256;
            int row = idx >> 4, c8 = idx & 15;
            uint32_t off = (row * SK + c8 * 8) * 2;
            int go = row * HDIM + c8 * 8;
            cp_async16(sKh + off, kh_p + go);
            cp_async16(sKl + off, kl_p + go);
            cp_async16(sVh + off, vh_p + go);
            cp_async16(sVl + off, vl_p + go);
        }
        CP_COMMIT();
        CP_WAIT(0);
        __syncthreads();

        // ---- S = Q K^T (bf16, 3 passes) ----
        float s[16][4];
#pragma unroll
        for (int t = 0; t < 16; t++)
#pragma unroll
            for (int j = 0; j < 4; j++) s[t][j] = 0.f;

#pragma unroll
        for (int kk = 0; kk < 8; kk++) {
            uint32_t qa[4], qb[4];
            uint32_t aoff = (a_r * SK + kk * 16 + a_c8 * 8) * 2;
            ldsm_x4(qa, sQh + aoff);
            ldsm_x4(qb, sQl + aoff);
#pragma unroll
            for (int nt = 0; nt < 8; nt++) {
                uint32_t kf[4], kg2[4];
                uint32_t boff = ((nt * 16 + kb_r) * SK + kk * 16 + kb_c8 * 8) * 2;
                ldsm_x4(kf, sKh + boff);
                ldsm_x4(kg2, sKl + boff);
                mma_bf16(s[2 * nt], qa, kf);
                mma_bf16(s[2 * nt], qa, kg2);
                mma_bf16(s[2 * nt], qb, kf);
                mma_bf16(s[2 * nt + 1], qa, kf + 2);
                mma_bf16(s[2 * nt + 1], qa, kg2 + 2);
                mma_bf16(s[2 * nt + 1], qb, kf + 2);
            }
        }

        // ---- online softmax ----
        float tm0 = -1e30f, tm1 = -1e30f;
#pragma unroll
        for (int t = 0; t < 16; t++) {
            tm0 = fmaxf(tm0, fmaxf(s[t][0], s[t][1]));
            tm1 = fmaxf(tm1, fmaxf(s[t][2], s[t][3]));
        }
        tm0 = fmaxf(tm0, __shfl_xor_sync(0xffffffffu, tm0, 1));
        tm0 = fmaxf(tm0, __shfl_xor_sync(0xffffffffu, tm0, 2));
        tm1 = fmaxf(tm1, __shfl_xor_sync(0xffffffffu, tm1, 1));
        tm1 = fmaxf(tm1, __shfl_xor_sync(0xffffffffu, tm1, 2));
        float mn0 = fmaxf(mrow0, tm0), mn1 = fmaxf(mrow1, tm1);
        float fac0 = __expf(mrow0 - mn0), fac1 = __expf(mrow1 - mn1);
        mrow0 = mn0; mrow1 = mn1;

        const float mnl0 = mn0 * LOG2E, mnl1 = mn1 * LOG2E;
        uint32_t ph[16][2];
#pragma unroll
        for (int t = 0; t < 16; t++) {
            float e0 = fmaf(s[t][0], LOG2E, -mnl0);
            float e1 = fmaf(s[t][1], LOG2E, -mnl0);
            float e2 = fmaf(s[t][2], LOG2E, -mnl1);
            float e3 = fmaf(s[t][3], LOG2E, -mnl1);
            ph[t][0] = h2exp2(packh2(e0, e1));
            ph[t][1] = h2exp2(packh2(e2, e3));
        }

        // ---- row sums via P * ones ----
        float lacc[4] = {0.f, 0.f, 0.f, 0.f};
#pragma unroll
        for (int kk = 0; kk < 8; kk++) {
            uint32_t ah[4] = {ph[2 * kk][0], ph[2 * kk][1],
                              ph[2 * kk + 1][0], ph[2 * kk + 1][1]};
            mma_f16(lacc, ah, bones);
        }
        lrow0 = lrow0 * fac0 + lacc[0];
        lrow1 = lrow1 * fac1 + lacc[2];

#pragma unroll
        for (int t = 0; t < 16; t++) {
            o[t][0] *= fac0; o[t][1] *= fac0;
            o[t][2] *= fac1; o[t][3] *= fac1;
        }

        // ---- O += P V (fp16, 2 passes) ----
#pragma unroll
        for (int kk = 0; kk < 8; kk++) {
            uint32_t ah[4] = {ph[2 * kk][0], ph[2 * kk][1],
                              ph[2 * kk + 1][0], ph[2 * kk + 1][1]};
#pragma unroll
            for (int nt = 0; nt < 8; nt++) {
                uint32_t vf[4], vg[4];
                uint32_t voff = ((kk * 16 + v_r) * SK + nt * 16 + v_c8 * 8) * 2;
                ldsm_x4_t(vf, sVh + voff);
                ldsm_x4_t(vg, sVl + voff);
                mma_f16(o[2 * nt], ah, vf);
                mma_f16(o[2 * nt], ah, vg);
                mma_f16(o[2 * nt + 1], ah, vf + 2);
                mma_f16(o[2 * nt + 1], ah, vg + 2);
            }
        }
        __syncthreads();
    }

    const int b = bh >> 4, h = bh & 15;
    const int n0 = qt * 128 + wid * 16 + (lane >> 2);
    const float inv0 = 1.0f / lrow0, inv1 = 1.0f / lrow1;
    const size_t grow0 = (size_t)(b * NN + n0) * DIMM;
    const size_t grow1 = (size_t)(b * NN + n0 + 8) * DIMM;
#pragma unroll
    for (int t = 0; t < 16; t++) {
        int col = h * HDIM + t * 8 + (lane & 3) * 2;
        uint32_t hi0, lo0, hi1, lo1;
        split2(o[t][0] * inv0, o[t][1] * inv0, hi0, lo0);
        split2(o[t][2] * inv1, o[t][3] * inv1, hi1, lo1);
        *(uint32_t*)(Ohi + grow0 + col) = hi0;
        *(uint32_t*)(Olo + grow0 + col) = lo0;
        *(uint32_t*)(Ohi + grow1 + col) = hi1;
        *(uint32_t*)(Olo + grow1 + col) = lo1;
    }
}

// ============================================================================
// Launch
// ============================================================================
extern "C" void kernel_launch(void* const* d_in, const int* in_sizes, int n_in,
                              void* d_out, int out_size)
{
    const float* x     = (const float*)d_in[0];
    const float* Wqkv  = (const float*)d_in[1];
    const float* qg    = (const float*)d_in[2];
    const float* kg    = (const float*)d_in[3];
    const float* Wout  = (const float*)d_in[4];
    const float* freqs = (const float*)d_in[5];
    float* out = (float*)d_out;

    float* qkv;
    __nv_bfloat16 *qhi, *qlo, *khi, *klo;
    __half *vhi, *vlo;
    __nv_bfloat16 *xhi, *xlo, *w1hi, *w1lo, *w2hi, *w2lo, *aohi, *aolo;
    cudaGetSymbolAddress((void**)&qkv, g_qkv);
    cudaGetSymbolAddress((void**)&qhi, g_qhi);
    cudaGetSymbolAddress((void**)&qlo, g_qlo);
    cudaGetSymbolAddress((void**)&khi, g_khi);
    cudaGetSymbolAddress((void**)&klo, g_klo);
    cudaGetSymbolAddress((void**)&vhi, g_vhi);
    cudaGetSymbolAddress((void**)&vlo, g_vlo);
    cudaGetSymbolAddress((void**)&xhi, g_xhi);
    cudaGetSymbolAddress((void**)&xlo, g_xlo);
    cudaGetSymbolAddress((void**)&w1hi, g_w1hi);
    cudaGetSymbolAddress((void**)&w1lo, g_w1lo);
    cudaGetSymbolAddress((void**)&w2hi, g_w2hi);
    cudaGetSymbolAddress((void**)&w2lo, g_w2lo);
    cudaGetSymbolAddress((void**)&aohi, g_aohi);
    cudaGetSymbolAddress((void**)&aolo, g_aolo);

    cudaFuncSetAttribute(gemm_mma_split,
                         cudaFuncAttributeMaxDynamicSharedMemorySize, GEMM_SMEM);
    cudaFuncSetAttribute(attn_mma,
                         cudaFuncAttributeMaxDynamicSharedMemorySize, ATT_SMEM);

    // splits of inputs
    {
        int n4x = (MROWS * DIMM) / 4;
        split_bf16<<<n4x / 256, 256>>>(x, xhi, xlo, n4x);
        int n4w1 = (E3 * DIMM) / 4;
        split_bf16<<<n4w1 / 256, 256>>>(Wqkv, w1hi, w1lo, n4w1);
        int n4w2 = (DIMM * DIMM) / 4;
        split_bf16<<<n4w2 / 256, 256>>>(Wout, w2hi, w2lo, n4w2);
    }
    // 1. QKV GEMM
    {
        dim3 grid(E3 / 128, MROWS / 128);
        gemm_mma_split<<<grid, 256, GEMM_SMEM>>>(xhi, xlo, w1hi, w1lo, qkv, E3, DIMM);
    }
    // 2. RMSNorm + RoPE + scatter
    norm_rope_scatter<<<MROWS * HN, 128>>>(qkv, qg, kg, freqs);
    // 3. Attention
    attn_mma<<<BB * HN * 16, 256, ATT_SMEM>>>(qhi, qlo, khi, klo, vhi, vlo,
                                              aohi, aolo);
    // 4. out GEMM
    {
        dim3 grid(DIMM / 128, MROWS / 128);
        gemm_mma_split<<<grid, 256, GEMM_SMEM>>>(aohi, aolo, w2hi, w2lo, out, DIMM, DIMM);
    }
}

// round 13
// speedup vs baseline: 1.2697x; 1.0357x over previous
#include <cuda_runtime.h>
#include <cuda_bf16.h>
#include <cuda_fp16.h>
#include <cstdint>

// Problem constants
#define DIMM   2048
#define HN     16
#define HDIM   128
#define BB     2
#define NN     2048
#define E3     (3 * HN * HDIM)      // 6144
#define MROWS  (BB * NN)            // 4096
#define EPSV   1e-5f
#define QSCALE 0.08838834764831845f // 1/sqrt(128)
#define LOG2E  1.4426950408889634f

// ---------------- scratch (static device arrays; no allocation) -------------
__device__ __nv_bfloat16 g_qhi[(size_t)BB * HN * NN * HDIM];
__device__ __nv_bfloat16 g_qlo[(size_t)BB * HN * NN * HDIM];
__device__ __nv_bfloat16 g_khi[(size_t)BB * HN * NN * HDIM];
__device__ __nv_bfloat16 g_klo[(size_t)BB * HN * NN * HDIM];
__device__ __half        g_vhi[(size_t)BB * HN * NN * HDIM];
__device__ __half        g_vlo[(size_t)BB * HN * NN * HDIM];

__device__ __nv_bfloat16 g_xhi[(size_t)MROWS * DIMM];
__device__ __nv_bfloat16 g_xlo[(size_t)MROWS * DIMM];
__device__ __nv_bfloat16 g_w1hi[(size_t)E3 * DIMM];
__device__ __nv_bfloat16 g_w1lo[(size_t)E3 * DIMM];
__device__ __nv_bfloat16 g_w2hi[(size_t)DIMM * DIMM];
__device__ __nv_bfloat16 g_w2lo[(size_t)DIMM * DIMM];
__device__ __nv_bfloat16 g_aohi[(size_t)MROWS * DIMM];
__device__ __nv_bfloat16 g_aolo[(size_t)MROWS * DIMM];

// ============================================================================
// helpers
// ============================================================================
__device__ __forceinline__ uint32_t smem_u32(const void* p) {
    uint32_t a;
    asm("{ .reg .u64 t; cvta.to.shared.u64 t, %1; cvt.u32.u64 %0, t; }"
        : "=r"(a) : "l"(p));
    return a;
}
__device__ __forceinline__ void cp_async16(uint32_t dst, const void* src) {
    asm volatile("cp.async.cg.shared.global [%0], [%1], 16;"
                 :: "r"(dst), "l"(src));
}
#define CP_COMMIT() asm volatile("cp.async.commit_group;" ::: "memory")
#define CP_WAIT(n)  asm volatile("cp.async.wait_group %0;" :: "n"(n) : "memory")

__device__ __forceinline__ void ldsm_x4(uint32_t* r, uint32_t addr) {
    asm volatile("ldmatrix.sync.aligned.m8n8.x4.shared.b16 {%0,%1,%2,%3}, [%4];"
                 : "=r"(r[0]), "=r"(r[1]), "=r"(r[2]), "=r"(r[3]) : "r"(addr));
}
__device__ __forceinline__ void ldsm_x4_t(uint32_t* r, uint32_t addr) {
    asm volatile("ldmatrix.sync.aligned.m8n8.x4.trans.shared.b16 {%0,%1,%2,%3}, [%4];"
                 : "=r"(r[0]), "=r"(r[1]), "=r"(r[2]), "=r"(r[3]) : "r"(addr));
}
__device__ __forceinline__ void mma_bf16(float* c, const uint32_t* a,
                                         const uint32_t* b) {
    asm volatile(
        "mma.sync.aligned.m16n8k16.row.col.f32.bf16.bf16.f32 "
        "{%0,%1,%2,%3}, {%4,%5,%6,%7}, {%8,%9}, {%0,%1,%2,%3};"
        : "+f"(c[0]), "+f"(c[1]), "+f"(c[2]), "+f"(c[3])
        : "r"(a[0]), "r"(a[1]), "r"(a[2]), "r"(a[3]), "r"(b[0]), "r"(b[1]));
}
__device__ __forceinline__ void mma_f16(float* c, const uint32_t* a,
                                        const uint32_t* b) {
    asm volatile(
        "mma.sync.aligned.m16n8k16.row.col.f32.f16.f16.f32 "
        "{%0,%1,%2,%3}, {%4,%5,%6,%7}, {%8,%9}, {%0,%1,%2,%3};"
        : "+f"(c[0]), "+f"(c[1]), "+f"(c[2]), "+f"(c[3])
        : "r"(a[0]), "r"(a[1]), "r"(a[2]), "r"(a[3]), "r"(b[0]), "r"(b[1]));
}
__device__ __forceinline__ void split2(float x, float y, uint32_t& hi, uint32_t& lo) {
    __nv_bfloat16 hx = __float2bfloat16(x), hy = __float2bfloat16(y);
    float rx = x - __bfloat162float(hx), ry = y - __bfloat162float(hy);
    __nv_bfloat162 H; H.x = hx; H.y = hy;
    __nv_bfloat162 L; L.x = __float2bfloat16(rx); L.y = __float2bfloat16(ry);
    hi = *(uint32_t*)&H;
    lo = *(uint32_t*)&L;
}
__device__ __forceinline__ uint32_t packh2(float lo, float hi) {
    uint32_t r;
    asm("cvt.rn.f16x2.f32 %0, %1, %2;" : "=r"(r) : "f"(hi), "f"(lo));
    return r;
}
__device__ __forceinline__ uint32_t h2exp2(uint32_t x) {
    uint32_t d;
    asm("ex2.approx.f16x2 %0, %1;" : "=r"(d) : "r"(x));
    return d;
}
// swizzled offset for 64B rows: chunk c in 0..3 (16B units)
__device__ __forceinline__ uint32_t swz64(int row, int c) {
    return (uint32_t)(row * 64 + ((c ^ ((row >> 1) & 3)) << 4));
}

// ============================================================================
// fp32 -> bf16 hi/lo split
// ============================================================================
__global__ void __launch_bounds__(256) split_bf16(
    const float* __restrict__ in, __nv_bfloat16* __restrict__ hi,
    __nv_bfloat16* __restrict__ lo, int n4)
{
    int i = blockIdx.x * 256 + threadIdx.x;
    if (i >= n4) return;
    float4 v = ((const float4*)in)[i];
    union { __nv_bfloat16 b[4]; uint2 u; } H, L;
    float vv[4] = {v.x, v.y, v.z, v.w};
#pragma unroll
    for (int j = 0; j < 4; j++) {
        __nv_bfloat16 h = __float2bfloat16(vv[j]);
        H.b[j] = h;
        L.b[j] = __float2bfloat16(vv[j] - __bfloat162float(h));
    }
    ((uint2*)hi)[i] = H.u;
    ((uint2*)lo)[i] = L.u;
}

// ============================================================================
// GEMM mainloop configuration (R11, passing): CTA 128x128, BK=32, warp 32x64,
// 3-stage swizzled smem, one __syncthreads per k-iteration.
// ============================================================================
#define GMAT 8192
#define GSTAGE (4 * GMAT)
#define GEMM_SMEM (3 * GSTAGE)

// Mainloop body shared textually between the two GEMM kernels via macro.
#define GEMM_MAINLOOP(Ah, Al, Bh, Bl, K)                                       \
    const __nv_bfloat16* srcs[4] = {Ah, Al, Bh, Bl};                           \
    const int rowbase[4] = {bm, bm, bn, bn};                                   \
    auto issue_stage = [&](int stage, int kc) {                                \
        uint32_t sdst = sbase + stage * GSTAGE;                                \
        _Pragma("unroll")                                                      \
        for (int t = 0; t < 8; t++) {                                          \
            int idx = tid + t * 256;                                           \
            int mat = idx >> 9;                                                \
            int row = (idx >> 2) & 127;                                        \
            int c = idx & 3;                                                   \
            uint32_t dst = sdst + mat * GMAT + swz64(row, c);                  \
            const __nv_bfloat16* src =                                         \
                srcs[mat] + (size_t)(rowbase[mat] + row) * K + kc + c * 8;     \
            cp_async16(dst, src);                                              \
        }                                                                      \
        CP_COMMIT();                                                           \
    };                                                                         \
    float acc[2][8][4];                                                        \
    _Pragma("unroll")                                                          \
    for (int a = 0; a < 2; a++)                                                \
        _Pragma("unroll")                                                      \
        for (int b = 0; b < 8; b++)                                            \
            _Pragma("unroll")                                                  \
            for (int c = 0; c < 4; c++) acc[a][b][c] = 0.f;                    \
    const int nk = (K) / 32;                                                   \
    issue_stage(0, 0);                                                         \
    issue_stage(1, 32);                                                        \
    const int a_r = warp_m * 32 + (lane & 15);                                 \
    const int a_c8 = lane >> 4;                                                \
    const int b_r = warp_n * 64 + (lane & 7) + (lane >> 4) * 8;                \
    const int b_c8 = (lane >> 3) & 1;                                          \
    for (int kb = 0; kb < nk; kb++) {                                          \
        if (kb < nk - 1) { CP_WAIT(1); } else { CP_WAIT(0); }                  \
        __syncthreads();                                                       \
        if (kb + 2 < nk) issue_stage((kb + 2) % 3, (kb + 2) * 32);             \
        const uint32_t st = sbase + (kb % 3) * GSTAGE;                         \
        const uint32_t sAh = st;                                               \
        const uint32_t sAl = st + GMAT;                                        \
        const uint32_t sBh = st + 2 * GMAT;                                    \
        const uint32_t sBl = st + 3 * GMAT;                                    \
        _Pragma("unroll")                                                      \
        for (int ks = 0; ks < 2; ks++) {                                       \
            uint32_t ahi[2][4], alo[2][4];                                     \
            _Pragma("unroll")                                                  \
            for (int tm = 0; tm < 2; tm++) {                                   \
                uint32_t off = swz64(a_r + tm * 16, ks * 2 + a_c8);            \
                ldsm_x4(ahi[tm], sAh + off);                                   \
                ldsm_x4(alo[tm], sAl + off);                                   \
            }                                                                  \
            _Pragma("unroll")                                                  \
            for (int g = 0; g < 4; g++) {                                      \
                uint32_t bhi[4], blo[4];                                       \
                uint32_t off = swz64(b_r + g * 16, ks * 2 + b_c8);             \
                ldsm_x4(bhi, sBh + off);                                       \
                ldsm_x4(blo, sBl + off);                                       \
                _Pragma("unroll")                                              \
                for (int tm = 0; tm < 2; tm++)                                 \
                    _Pragma("unroll")                                          \
                    for (int sub = 0; sub < 2; sub++)                          \
                        mma_bf16(acc[tm][g * 2 + sub], ahi[tm], bhi + sub * 2);\
                _Pragma("unroll")                                              \
                for (int tm = 0; tm < 2; tm++)                                 \
                    _Pragma("unroll")                                          \
                    for (int sub = 0; sub < 2; sub++)                          \
                        mma_bf16(acc[tm][g * 2 + sub], ahi[tm], blo + sub * 2);\
                _Pragma("unroll")                                              \
                for (int tm = 0; tm < 2; tm++)                                 \
                    _Pragma("unroll")                                          \
                    for (int sub = 0; sub < 2; sub++)                          \
                        mma_bf16(acc[tm][g * 2 + sub], alo[tm], bhi + sub * 2);\
            }                                                                  \
        }                                                                      \
    }

// ============================================================================
// Plain GEMM (out projection): writes fp32 C.
// ============================================================================
__global__ void __launch_bounds__(256, 2) gemm_mma_split(
    const __nv_bfloat16* __restrict__ Ah, const __nv_bfloat16* __restrict__ Al,
    const __nv_bfloat16* __restrict__ Bh, const __nv_bfloat16* __restrict__ Bl,
    float* __restrict__ C, int Ntot, int K)
{
    extern __shared__ __align__(128) char sm[];
    const uint32_t sbase = smem_u32(sm);
    const int tid = threadIdx.x;
    const int lane = tid & 31;
    const int wid = tid >> 5;
    const int warp_m = wid & 3;
    const int warp_n = wid >> 2;
    const int bm = blockIdx.y * 128;
    const int bn = blockIdx.x * 128;

    GEMM_MAINLOOP(Ah, Al, Bh, Bl, K)

    const int crow = lane >> 2;
    const int ccol = (lane & 3) * 2;
#pragma unroll
    for (int tm = 0; tm < 2; tm++) {
#pragma unroll
        for (int t = 0; t < 8; t++) {
            int row = bm + warp_m * 32 + tm * 16 + crow;
            int col = bn + warp_n * 64 + t * 8 + ccol;
            float* p0 = C + (size_t)row * Ntot + col;
            float* p1 = C + (size_t)(row + 8) * Ntot + col;
            p0[0] = acc[tm][t][0]; p0[1] = acc[tm][t][1];
            p1[0] = acc[tm][t][2]; p1[1] = acc[tm][t][3];
        }
    }
}

// ============================================================================
// QKV GEMM with fused RMSNorm + RoPE + split-scatter epilogue.
// Tile cols [bn, bn+128) = exactly one head of q, k, or v.
// ============================================================================
__global__ void __launch_bounds__(256, 2) gemm_qkv_fused(
    const __nv_bfloat16* __restrict__ Ah, const __nv_bfloat16* __restrict__ Al,
    const __nv_bfloat16* __restrict__ Bh, const __nv_bfloat16* __restrict__ Bl,
    const float* __restrict__ qg, const float* __restrict__ kgm,
    const float* __restrict__ freqs,
    __nv_bfloat16* __restrict__ Qhi, __nv_bfloat16* __restrict__ Qlo,
    __nv_bfloat16* __restrict__ Khi, __nv_bfloat16* __restrict__ Klo,
    __half* __restrict__ Vhi, __half* __restrict__ Vlo)
{
    extern __shared__ __align__(128) char sm[];
    __shared__ float red[128][2];
    const uint32_t sbase = smem_u32(sm);
    const int tid = threadIdx.x;
    const int lane = tid & 31;
    const int wid = tid >> 5;
    const int warp_m = wid & 3;
    const int warp_n = wid >> 2;
    const int bm = blockIdx.y * 128;
    const int bn = blockIdx.x * 128;
    const int K = DIMM;

    GEMM_MAINLOOP(Ah, Al, Bh, Bl, K)

    const int crow = lane >> 2;
    const int ccol = (lane & 3) * 2;
    const int region = bn >> 11;        // 0 = q, 1 = k, 2 = v
    const int h = (bn >> 7) & 15;

    if (region == 2) {
        // V head: fp16 hi/lo split, no norm
#pragma unroll
        for (int tm = 0; tm < 2; tm++) {
#pragma unroll
            for (int t = 0; t < 8; t++) {
                int d = warp_n * 64 + t * 8 + ccol;
#pragma unroll
                for (int rh = 0; rh < 2; rh++) {
                    int row = bm + warp_m * 32 + tm * 16 + crow + rh * 8;
                    float v0 = acc[tm][t][rh * 2 + 0];
                    float v1 = acc[tm][t][rh * 2 + 1];
                    int b = row >> 11, n = row & (NN - 1);
                    size_t dst = ((size_t)(b * HN + h) * NN + n) * HDIM + d;
                    __half h0 = __float2half_rn(v0), h1 = __float2half_rn(v1);
                    __half2 H; H.x = h0; H.y = h1;
                    __half2 L;
                    L.x = __float2half_rn(v0 - __half2float(h0));
                    L.y = __float2half_rn(v1 - __half2float(h1));
                    *(uint32_t*)(Vhi + dst) = *(uint32_t*)&H;
                    *(uint32_t*)(Vlo + dst) = *(uint32_t*)&L;
                }
            }
        }
    } else {
        // Q/K head: per-row sumsq -> rsqrt -> gamma(-scale) -> RoPE -> split
#pragma unroll
        for (int tm = 0; tm < 2; tm++) {
            float p0 = 0.f, p1 = 0.f;
#pragma unroll
            for (int t = 0; t < 8; t++) {
                p0 = fmaf(acc[tm][t][0], acc[tm][t][0], p0);
                p0 = fmaf(acc[tm][t][1], acc[tm][t][1], p0);
                p1 = fmaf(acc[tm][t][2], acc[tm][t][2], p1);
                p1 = fmaf(acc[tm][t][3], acc[tm][t][3], p1);
            }
            p0 += __shfl_xor_sync(0xffffffffu, p0, 1);
            p0 += __shfl_xor_sync(0xffffffffu, p0, 2);
            p1 += __shfl_xor_sync(0xffffffffu, p1, 1);
            p1 += __shfl_xor_sync(0xffffffffu, p1, 2);
            if ((lane & 3) == 0) {
                red[warp_m * 32 + tm * 16 + (lane >> 2)][warp_n] = p0;
                red[warp_m * 32 + tm * 16 + (lane >> 2) + 8][warp_n] = p1;
            }
        }
        __syncthreads();

        const float* gam = (region == 0) ? qg : kgm;
        const float qs = (region == 0) ? QSCALE : 1.0f;
        __nv_bfloat16* Dhi = (region == 0) ? Qhi : Khi;
        __nv_bfloat16* Dlo = (region == 0) ? Qlo : Klo;

#pragma unroll
        for (int tm = 0; tm < 2; tm++) {
#pragma unroll
            for (int rh = 0; rh < 2; rh++) {
                int lrow = warp_m * 32 + tm * 16 + crow + rh * 8;
                int row = bm + lrow;
                float tot = red[lrow][0] + red[lrow][1];
                float rinv = rsqrtf(tot * (1.0f / HDIM) + EPSV) * qs;
                int b = row >> 11, n = row & (NN - 1);
                const float* fr = freqs + (size_t)row * 128;   // [m][64][2]
                size_t obase = ((size_t)(b * HN + h) * NN + n) * HDIM;
#pragma unroll
                for (int t = 0; t < 8; t++) {
                    int d = warp_n * 64 + t * 8 + ccol;
                    int i = d >> 1;
                    float x0 = acc[tm][t][rh * 2 + 0] * rinv * gam[d];
                    float x1 = acc[tm][t][rh * 2 + 1] * rinv * gam[d + 1];
                    float cs = fr[i * 2 + 0], sn = fr[i * 2 + 1];
                    float y0 = x0 * cs - x1 * sn;
                    float y1 = x0 * sn + x1 * cs;
                    uint32_t hi, lo;
                    split2(y0, y1, hi, lo);
                    *(uint32_t*)(Dhi + obase + d) = hi;
                    *(uint32_t*)(Dlo + obase + d) = lo;
                }
            }
        }
    }
}

// ============================================================================
// Flash attention (R11 version verbatim — passing): QK bf16 3-pass,
// fp16 ex2 softmax, PV fp16 2-pass, P*ones row sums, CP_WAIT(0) per tile.
// ============================================================================
#define SK 136
#define ATT_MAT (128 * SK * 2)
#define ATT_SMEM (6 * ATT_MAT)

__global__ void __launch_bounds__(256, 1) attn_mma(
    const __nv_bfloat16* __restrict__ Qh, const __nv_bfloat16* __restrict__ Ql,
    const __nv_bfloat16* __restrict__ Kh, const __nv_bfloat16* __restrict__ Kl,
    const __half* __restrict__ Vh, const __half* __restrict__ Vl,
    __nv_bfloat16* __restrict__ Ohi, __nv_bfloat16* __restrict__ Olo)
{
    extern __shared__ __align__(128) char smA[];
    const uint32_t sbase = smem_u32(smA);
    const uint32_t sQh = sbase, sQl = sbase + ATT_MAT;
    const uint32_t sKh = sbase + 2 * ATT_MAT, sKl = sbase + 3 * ATT_MAT;
    const uint32_t sVh = sbase + 4 * ATT_MAT, sVl = sbase + 5 * ATT_MAT;

    const int tid = threadIdx.x;
    const int lane = tid & 31;
    const int wid = tid >> 5;
    const int qt = blockIdx.x & 15;
    const int bh = blockIdx.x >> 4;

    const size_t seqbase = (size_t)bh * NN * HDIM;
    const __nv_bfloat16* qh_p = Qh + seqbase + (size_t)qt * 128 * HDIM;
    const __nv_bfloat16* ql_p = Ql + seqbase + (size_t)qt * 128 * HDIM;

    {
#pragma unroll
        for (int t = 0; t < 8; t++) {
            int idx = tid + t * 256;
            int row = idx >> 4, c8 = idx & 15;
            uint32_t off = (row * SK + c8 * 8) * 2;
            cp_async16(sQh + off, qh_p + row * HDIM + c8 * 8);
            cp_async16(sQl + off, ql_p + row * HDIM + c8 * 8);
        }
        CP_COMMIT();
    }

    float o[16][4];
#pragma unroll
    for (int t = 0; t < 16; t++)
#pragma unroll
        for (int j = 0; j < 4; j++) o[t][j] = 0.f;
    float mrow0 = -1e30f, mrow1 = -1e30f, lrow0 = 0.f, lrow1 = 0.f;

    const uint32_t ones2 = 0x3C003C00u;
    const uint32_t bones[2] = {ones2, ones2};

    const int a_r = wid * 16 + (lane & 15);
    const int a_c8 = lane >> 4;
    const int kb_r = (lane & 7) + (lane >> 4) * 8;
    const int kb_c8 = (lane >> 3) & 1;
    const int v_r = lane & 15;
    const int v_c8 = lane >> 4;

    for (int t0 = 0; t0 < NN; t0 += 128) {
        const __nv_bfloat16* kh_p = Kh + seqbase + (size_t)t0 * HDIM;
        const __nv_bfloat16* kl_p = Kl + seqbase + (size_t)t0 * HDIM;
        const __half* vh_p = Vh + seqbase + (size_t)t0 * HDIM;
        const __half* vl_p = Vl + seqbase + (size_t)t0 * HDIM;
#pragma unroll
        for (int t = 0; t < 8; t++) {
            int idx = tid + t * 256;
            int row = idx >> 4, c8 = idx & 15;
            uint32_t off = (row * SK + c8 * 8) * 2;
            int go = row * HDIM + c8 * 8;
            cp_async16(sKh + off, kh_p + go);
            cp_async16(sKl + off, kl_p + go);
            cp_async16(sVh + off, vh_p + go);
            cp_async16(sVl + off, vl_p + go);
        }
        CP_COMMIT();
        CP_WAIT(0);
        __syncthreads();

        float s[16][4];
#pragma unroll
        for (int t = 0; t < 16; t++)
#pragma unroll
            for (int j = 0; j < 4; j++) s[t][j] = 0.f;

#pragma unroll
        for (int kk = 0; kk < 8; kk++) {
            uint32_t qa[4], qb[4];
            uint32_t aoff = (a_r * SK + kk * 16 + a_c8 * 8) * 2;
            ldsm_x4(qa, sQh + aoff);
            ldsm_x4(qb, sQl + aoff);
#pragma unroll
            for (int nt = 0; nt < 8; nt++) {
                uint32_t kf[4], kg2[4];
                uint32_t boff = ((nt * 16 + kb_r) * SK + kk * 16 + kb_c8 * 8) * 2;
                ldsm_x4(kf, sKh + boff);
                ldsm_x4(kg2, sKl + boff);
                mma_bf16(s[2 * nt], qa, kf);
                mma_bf16(s[2 * nt], qa, kg2);
                mma_bf16(s[2 * nt], qb, kf);
                mma_bf16(s[2 * nt + 1], qa, kf + 2);
                mma_bf16(s[2 * nt + 1], qa, kg2 + 2);
                mma_bf16(s[2 * nt + 1], qb, kf + 2);
            }
        }

        float tm0 = -1e30f, tm1 = -1e30f;
#pragma unroll
        for (int t = 0; t < 16; t++) {
            tm0 = fmaxf(tm0, fmaxf(s[t][0], s[t][1]));
            tm1 = fmaxf(tm1, fmaxf(s[t][2], s[t][3]));
        }
        tm0 = fmaxf(tm0, __shfl_xor_sync(0xffffffffu, tm0, 1));
        tm0 = fmaxf(tm0, __shfl_xor_sync(0xffffffffu, tm0, 2));
        tm1 = fmaxf(tm1, __shfl_xor_sync(0xffffffffu, tm1, 1));
        tm1 = fmaxf(tm1, __shfl_xor_sync(0xffffffffu, tm1, 2));
        float mn0 = fmaxf(mrow0, tm0), mn1 = fmaxf(mrow1, tm1);
        float fac0 = __expf(mrow0 - mn0), fac1 = __expf(mrow1 - mn1);
        mrow0 = mn0; mrow1 = mn1;

        const float mnl0 = mn0 * LOG2E, mnl1 = mn1 * LOG2E;
        uint32_t ph[16][2];
#pragma unroll
        for (int t = 0; t < 16; t++) {
            float e0 = fmaf(s[t][0], LOG2E, -mnl0);
            float e1 = fmaf(s[t][1], LOG2E, -mnl0);
            float e2 = fmaf(s[t][2], LOG2E, -mnl1);
            float e3 = fmaf(s[t][3], LOG2E, -mnl1);
            ph[t][0] = h2exp2(packh2(e0, e1));
            ph[t][1] = h2exp2(packh2(e2, e3));
        }

        float lacc[4] = {0.f, 0.f, 0.f, 0.f};
#pragma unroll
        for (int kk = 0; kk < 8; kk++) {
            uint32_t ah[4] = {ph[2 * kk][0], ph[2 * kk][1],
                              ph[2 * kk + 1][0], ph[2 * kk + 1][1]};
            mma_f16(lacc, ah, bones);
        }
        lrow0 = lrow0 * fac0 + lacc[0];
        lrow1 = lrow1 * fac1 + lacc[2];

#pragma unroll
        for (int t = 0; t < 16; t++) {
            o[t][0] *= fac0; o[t][1] *= fac0;
            o[t][2] *= fac1; o[t][3] *= fac1;
        }

#pragma unroll
        for (int kk = 0; kk < 8; kk++) {
            uint32_t ah[4] = {ph[2 * kk][0], ph[2 * kk][1],
                              ph[2 * kk + 1][0], ph[2 * kk + 1][1]};
#pragma unroll
            for (int nt = 0; nt < 8; nt++) {
                uint32_t vf[4], vg[4];
                uint32_t voff = ((kk * 16 + v_r) * SK + nt * 16 + v_c8 * 8) * 2;
                ldsm_x4_t(vf, sVh + voff);
                ldsm_x4_t(vg, sVl + voff);
                mma_f16(o[2 * nt], ah, vf);
                mma_f16(o[2 * nt], ah, vg);
                mma_f16(o[2 * nt + 1], ah, vf + 2);
                mma_f16(o[2 * nt + 1], ah, vg + 2);
            }
        }
        __syncthreads();
    }

    const int b = bh >> 4, h = bh & 15;
    const int n0 = qt * 128 + wid * 16 + (lane >> 2);
    const float inv0 = 1.0f / lrow0, inv1 = 1.0f / lrow1;
    const size_t grow0 = (size_t)(b * NN + n0) * DIMM;
    const size_t grow1 = (size_t)(b * NN + n0 + 8) * DIMM;
#pragma unroll
    for (int t = 0; t < 16; t++) {
        int col = h * HDIM + t * 8 + (lane & 3) * 2;
        uint32_t hi0, lo0, hi1, lo1;
        split2(o[t][0] * inv0, o[t][1] * inv0, hi0, lo0);
        split2(o[t][2] * inv1, o[t][3] * inv1, hi1, lo1);
        *(uint32_t*)(Ohi + grow0 + col) = hi0;
        *(uint32_t*)(Olo + grow0 + col) = lo0;
        *(uint32_t*)(Ohi + grow1 + col) = hi1;
        *(uint32_t*)(Olo + grow1 + col) = lo1;
    }
}

// ============================================================================
// Launch
// ============================================================================
extern "C" void kernel_launch(void* const* d_in, const int* in_sizes, int n_in,
                              void* d_out, int out_size)
{
    const float* x     = (const float*)d_in[0];
    const float* Wqkv  = (const float*)d_in[1];
    const float* qg    = (const float*)d_in[2];
    const float* kg    = (const float*)d_in[3];
    const float* Wout  = (const float*)d_in[4];
    const float* freqs = (const float*)d_in[5];
    float* out = (float*)d_out;

    __nv_bfloat16 *qhi, *qlo, *khi, *klo;
    __half *vhi, *vlo;
    __nv_bfloat16 *xhi, *xlo, *w1hi, *w1lo, *w2hi, *w2lo, *aohi, *aolo;
    cudaGetSymbolAddress((void**)&qhi, g_qhi);
    cudaGetSymbolAddress((void**)&qlo, g_qlo);
    cudaGetSymbolAddress((void**)&khi, g_khi);
    cudaGetSymbolAddress((void**)&klo, g_klo);
    cudaGetSymbolAddress((void**)&vhi, g_vhi);
    cudaGetSymbolAddress((void**)&vlo, g_vlo);
    cudaGetSymbolAddress((void**)&xhi, g_xhi);
    cudaGetSymbolAddress((void**)&xlo, g_xlo);
    cudaGetSymbolAddress((void**)&w1hi, g_w1hi);
    cudaGetSymbolAddress((void**)&w1lo, g_w1lo);
    cudaGetSymbolAddress((void**)&w2hi, g_w2hi);
    cudaGetSymbolAddress((void**)&w2lo, g_w2lo);
    cudaGetSymbolAddress((void**)&aohi, g_aohi);
    cudaGetSymbolAddress((void**)&aolo, g_aolo);

    cudaFuncSetAttribute(gemm_mma_split,
                         cudaFuncAttributeMaxDynamicSharedMemorySize, GEMM_SMEM);
    cudaFuncSetAttribute(gemm_qkv_fused,
                         cudaFuncAttributeMaxDynamicSharedMemorySize, GEMM_SMEM);
    cudaFuncSetAttribute(attn_mma,
                         cudaFuncAttributeMaxDynamicSharedMemorySize, ATT_SMEM);

    // splits of inputs
    {
        int n4x = (MROWS * DIMM) / 4;
        split_bf16<<<n4x / 256, 256>>>(x, xhi, xlo, n4x);
        int n4w1 = (E3 * DIMM) / 4;
        split_bf16<<<n4w1 / 256, 256>>>(Wqkv, w1hi, w1lo, n4w1);
        int n4w2 = (DIMM * DIMM) / 4;
        split_bf16<<<n4w2 / 256, 256>>>(Wout, w2hi, w2lo, n4w2);
    }
    // 1. QKV GEMM with fused RMSNorm + RoPE + split scatter
    {
        dim3 grid(E3 / 128, MROWS / 128);
        gemm_qkv_fused<<<grid, 256, GEMM_SMEM>>>(
            xhi, xlo, w1hi, w1lo, qg, kg, freqs,
            qhi, qlo, khi, klo, vhi, vlo);
    }
    // 2. Attention
    attn_mma<<<BB * HN * 16, 256, ATT_SMEM>>>(qhi, qlo, khi, klo, vhi, vlo,
                                              aohi, aolo);
    // 3. out GEMM
    {
        dim3 grid(DIMM / 128, MROWS / 128);
        gemm_mma_split<<<grid, 256, GEMM_SMEM>>>(aohi, aolo, w2hi, w2lo, out, DIMM, DIMM);
    }
}

// round 16
// speedup vs baseline: 1.2970x; 1.0214x over previous
#include <cuda_runtime.h>
#include <cuda_bf16.h>
#include <cuda_fp16.h>
#include <cstdint>

// Problem constants
#define DIMM   2048
#define HN     16
#define HDIM   128
#define BB     2
#define NN     2048
#define E3     (3 * HN * HDIM)      // 6144
#define MROWS  (BB * NN)            // 4096
#define EPSV   1e-5f
#define QSCALE 0.08838834764831845f // 1/sqrt(128)
#define LOG2E  1.4426950408889634f

// ---------------- scratch (static device arrays; no allocation) -------------
__device__ __nv_bfloat16 g_qhi[(size_t)BB * HN * NN * HDIM];
__device__ __nv_bfloat16 g_qlo[(size_t)BB * HN * NN * HDIM];
__device__ __nv_bfloat16 g_khi[(size_t)BB * HN * NN * HDIM];
__device__ __nv_bfloat16 g_klo[(size_t)BB * HN * NN * HDIM];
__device__ __half        g_vhi[(size_t)BB * HN * NN * HDIM];
__device__ __half        g_vlo[(size_t)BB * HN * NN * HDIM];

__device__ __nv_bfloat16 g_xhi[(size_t)MROWS * DIMM];
__device__ __nv_bfloat16 g_xlo[(size_t)MROWS * DIMM];
__device__ __nv_bfloat16 g_w1hi[(size_t)E3 * DIMM];
__device__ __nv_bfloat16 g_w1lo[(size_t)E3 * DIMM];
__device__ __nv_bfloat16 g_w2hi[(size_t)DIMM * DIMM];
__device__ __nv_bfloat16 g_w2lo[(size_t)DIMM * DIMM];
__device__ __nv_bfloat16 g_aohi[(size_t)MROWS * DIMM];
__device__ __nv_bfloat16 g_aolo[(size_t)MROWS * DIMM];

// ============================================================================
// helpers
// ============================================================================
__device__ __forceinline__ uint32_t smem_u32(const void* p) {
    uint32_t a;
    asm("{ .reg .u64 t; cvta.to.shared.u64 t, %1; cvt.u32.u64 %0, t; }"
        : "=r"(a) : "l"(p));
    return a;
}
__device__ __forceinline__ void cp_async16(uint32_t dst, const void* src) {
    asm volatile("cp.async.cg.shared.global [%0], [%1], 16;"
                 :: "r"(dst), "l"(src));
}
#define CP_COMMIT() asm volatile("cp.async.commit_group;" ::: "memory")
#define CP_WAIT(n)  asm volatile("cp.async.wait_group %0;" :: "n"(n) : "memory")

__device__ __forceinline__ void ldsm_x4(uint32_t* r, uint32_t addr) {
    asm volatile("ldmatrix.sync.aligned.m8n8.x4.shared.b16 {%0,%1,%2,%3}, [%4];"
                 : "=r"(r[0]), "=r"(r[1]), "=r"(r[2]), "=r"(r[3]) : "r"(addr));
}
__device__ __forceinline__ void ldsm_x4_t(uint32_t* r, uint32_t addr) {
    asm volatile("ldmatrix.sync.aligned.m8n8.x4.trans.shared.b16 {%0,%1,%2,%3}, [%4];"
                 : "=r"(r[0]), "=r"(r[1]), "=r"(r[2]), "=r"(r[3]) : "r"(addr));
}
__device__ __forceinline__ void mma_bf16(float* c, const uint32_t* a,
                                         const uint32_t* b) {
    asm volatile(
        "mma.sync.aligned.m16n8k16.row.col.f32.bf16.bf16.f32 "
        "{%0,%1,%2,%3}, {%4,%5,%6,%7}, {%8,%9}, {%0,%1,%2,%3};"
        : "+f"(c[0]), "+f"(c[1]), "+f"(c[2]), "+f"(c[3])
        : "r"(a[0]), "r"(a[1]), "r"(a[2]), "r"(a[3]), "r"(b[0]), "r"(b[1]));
}
__device__ __forceinline__ void mma_f16(float* c, const uint32_t* a,
                                        const uint32_t* b) {
    asm volatile(
        "mma.sync.aligned.m16n8k16.row.col.f32.f16.f16.f32 "
        "{%0,%1,%2,%3}, {%4,%5,%6,%7}, {%8,%9}, {%0,%1,%2,%3};"
        : "+f"(c[0]), "+f"(c[1]), "+f"(c[2]), "+f"(c[3])
        : "r"(a[0]), "r"(a[1]), "r"(a[2]), "r"(a[3]), "r"(b[0]), "r"(b[1]));
}
__device__ __forceinline__ void split2(float x, float y, uint32_t& hi, uint32_t& lo) {
    __nv_bfloat16 hx = __float2bfloat16(x), hy = __float2bfloat16(y);
    float rx = x - __bfloat162float(hx), ry = y - __bfloat162float(hy);
    __nv_bfloat162 H; H.x = hx; H.y = hy;
    __nv_bfloat162 L; L.x = __float2bfloat16(rx); L.y = __float2bfloat16(ry);
    hi = *(uint32_t*)&H;
    lo = *(uint32_t*)&L;
}
__device__ __forceinline__ uint32_t packh2(float lo, float hi) {
    uint32_t r;
    asm("cvt.rn.f16x2.f32 %0, %1, %2;" : "=r"(r) : "f"(hi), "f"(lo));
    return r;
}
__device__ __forceinline__ uint32_t h2exp2(uint32_t x) {
    uint32_t d;
    asm("ex2.approx.f16x2 %0, %1;" : "=r"(d) : "r"(x));
    return d;
}
// swizzled offset for 64B rows: chunk c in 0..3 (16B units)
__device__ __forceinline__ uint32_t swz64(int row, int c) {
    return (uint32_t)(row * 64 + ((c ^ ((row >> 1) & 3)) << 4));
}

// ============================================================================
// fp32 -> bf16 hi/lo split
// ============================================================================
__global__ void __launch_bounds__(256) split_bf16(
    const float* __restrict__ in, __nv_bfloat16* __restrict__ hi,
    __nv_bfloat16* __restrict__ lo, int n4)
{
    int i = blockIdx.x * 256 + threadIdx.x;
    if (i >= n4) return;
    float4 v = ((const float4*)in)[i];
    union { __nv_bfloat16 b[4]; uint2 u; } H, L;
    float vv[4] = {v.x, v.y, v.z, v.w};
#pragma unroll
    for (int j = 0; j < 4; j++) {
        __nv_bfloat16 h = __float2bfloat16(vv[j]);
        H.b[j] = h;
        L.b[j] = __float2bfloat16(vv[j] - __bfloat162float(h));
    }
    ((uint2*)hi)[i] = H.u;
    ((uint2*)lo)[i] = L.u;
}

// ============================================================================
// GEMM mainloop (R11/R13, passing): CTA 128x128, BK=32, warp 32x64,
// 3-stage swizzled smem, one __syncthreads per k-iteration.
// ============================================================================
#define GMAT 8192
#define GSTAGE (4 * GMAT)
#define GEMM_SMEM (3 * GSTAGE)

#define GEMM_MAINLOOP(Ah, Al, Bh, Bl, K)                                       \
    const __nv_bfloat16* srcs[4] = {Ah, Al, Bh, Bl};                           \
    const int rowbase[4] = {bm, bm, bn, bn};                                   \
    auto issue_stage = [&](int stage, int kc) {                                \
        uint32_t sdst = sbase + stage * GSTAGE;                                \
        _Pragma("unroll")                                                      \
        for (int t = 0; t < 8; t++) {                                          \
            int idx = tid + t * 256;                                           \
            int mat = idx >> 9;                                                \
            int row = (idx >> 2) & 127;                                        \
            int c = idx & 3;                                                   \
            uint32_t dst = sdst + mat * GMAT + swz64(row, c);                  \
            const __nv_bfloat16* src =                                         \
                srcs[mat] + (size_t)(rowbase[mat] + row) * K + kc + c * 8;     \
            cp_async16(dst, src);                                              \
        }                                                                      \
        CP_COMMIT();                                                           \
    };                                                                         \
    float acc[2][8][4];                                                        \
    _Pragma("unroll")                                                          \
    for (int a = 0; a < 2; a++)                                                \
        _Pragma("unroll")                                                      \
        for (int b = 0; b < 8; b++)                                            \
            _Pragma("unroll")                                                  \
            for (int c = 0; c < 4; c++) acc[a][b][c] = 0.f;                    \
    const int nk = (K) / 32;                                                   \
    issue_stage(0, 0);                                                         \
    issue_stage(1, 32);                                                        \
    const int a_r = warp_m * 32 + (lane & 15);                                 \
    const int a_c8 = lane >> 4;                                                \
    const int b_r = warp_n * 64 + (lane & 7) + (lane >> 4) * 8;                \
    const int b_c8 = (lane >> 3) & 1;                                          \
    for (int kb = 0; kb < nk; kb++) {                                          \
        if (kb < nk - 1) { CP_WAIT(1); } else { CP_WAIT(0); }                  \
        __syncthreads();                                                       \
        if (kb + 2 < nk) issue_stage((kb + 2) % 3, (kb + 2) * 32);             \
        const uint32_t st = sbase + (kb % 3) * GSTAGE;                         \
        const uint32_t sAh = st;                                               \
        const uint32_t sAl = st + GMAT;                                        \
        const uint32_t sBh = st + 2 * GMAT;                                    \
        const uint32_t sBl = st + 3 * GMAT;                                    \
        _Pragma("unroll")                                                      \
        for (int ks = 0; ks < 2; ks++) {                                       \
            uint32_t ahi[2][4], alo[2][4];                                     \
            _Pragma("unroll")                                                  \
            for (int tm = 0; tm < 2; tm++) {                                   \
                uint32_t off = swz64(a_r + tm * 16, ks * 2 + a_c8);            \
                ldsm_x4(ahi[tm], sAh + off);                                   \
                ldsm_x4(alo[tm], sAl + off);                                   \
            }                                                                  \
            _Pragma("unroll")                                                  \
            for (int g = 0; g < 4; g++) {                                      \
                uint32_t bhi[4], blo[4];                                       \
                uint32_t off = swz64(b_r + g * 16, ks * 2 + b_c8);             \
                ldsm_x4(bhi, sBh + off);                                       \
                ldsm_x4(blo, sBl + off);                                       \
                _Pragma("unroll")                                              \
                for (int tm = 0; tm < 2; tm++)                                 \
                    _Pragma("unroll")                                          \
                    for (int sub = 0; sub < 2; sub++)                          \
                        mma_bf16(acc[tm][g * 2 + sub], ahi[tm], bhi + sub * 2);\
                _Pragma("unroll")                                              \
                for (int tm = 0; tm < 2; tm++)                                 \
                    _Pragma("unroll")                                          \
                    for (int sub = 0; sub < 2; sub++)                          \
                        mma_bf16(acc[tm][g * 2 + sub], ahi[tm], blo + sub * 2);\
                _Pragma("unroll")                                              \
                for (int tm = 0; tm < 2; tm++)                                 \
                    _Pragma("unroll")                                          \
                    for (int sub = 0; sub < 2; sub++)                          \
                        mma_bf16(acc[tm][g * 2 + sub], alo[tm], bhi + sub * 2);\
            }                                                                  \
        }                                                                      \
    }

// ============================================================================
// Plain GEMM (out projection): writes fp32 C.
// ============================================================================
__global__ void __launch_bounds__(256, 2) gemm_mma_split(
    const __nv_bfloat16* __restrict__ Ah, const __nv_bfloat16* __restrict__ Al,
    const __nv_bfloat16* __restrict__ Bh, const __nv_bfloat16* __restrict__ Bl,
    float* __restrict__ C, int Ntot, int K)
{
    extern __shared__ __align__(128) char sm[];
    const uint32_t sbase = smem_u32(sm);
    const int tid = threadIdx.x;
    const int lane = tid & 31;
    const int wid = tid >> 5;
    const int warp_m = wid & 3;
    const int warp_n = wid >> 2;
    const int bm = blockIdx.y * 128;
    const int bn = blockIdx.x * 128;

    GEMM_MAINLOOP(Ah, Al, Bh, Bl, K)

    const int crow = lane >> 2;
    const int ccol = (lane & 3) * 2;
#pragma unroll
    for (int tm = 0; tm < 2; tm++) {
#pragma unroll
        for (int t = 0; t < 8; t++) {
            int row = bm + warp_m * 32 + tm * 16 + crow;
            int col = bn + warp_n * 64 + t * 8 + ccol;
            float* p0 = C + (size_t)row * Ntot + col;
            float* p1 = C + (size_t)(row + 8) * Ntot + col;
            p0[0] = acc[tm][t][0]; p0[1] = acc[tm][t][1];
            p1[0] = acc[tm][t][2]; p1[1] = acc[tm][t][3];
        }
    }
}

// ============================================================================
// QKV GEMM with fused RMSNorm + RoPE + split-scatter epilogue (R13, passing).
// ============================================================================
__global__ void __launch_bounds__(256, 2) gemm_qkv_fused(
    const __nv_bfloat16* __restrict__ Ah, const __nv_bfloat16* __restrict__ Al,
    const __nv_bfloat16* __restrict__ Bh, const __nv_bfloat16* __restrict__ Bl,
    const float* __restrict__ qg, const float* __restrict__ kgm,
    const float* __restrict__ freqs,
    __nv_bfloat16* __restrict__ Qhi, __nv_bfloat16* __restrict__ Qlo,
    __nv_bfloat16* __restrict__ Khi, __nv_bfloat16* __restrict__ Klo,
    __half* __restrict__ Vhi, __half* __restrict__ Vlo)
{
    extern __shared__ __align__(128) char sm[];
    __shared__ float red[128][2];
    const uint32_t sbase = smem_u32(sm);
    const int tid = threadIdx.x;
    const int lane = tid & 31;
    const int wid = tid >> 5;
    const int warp_m = wid & 3;
    const int warp_n = wid >> 2;
    const int bm = blockIdx.y * 128;
    const int bn = blockIdx.x * 128;
    const int K = DIMM;

    GEMM_MAINLOOP(Ah, Al, Bh, Bl, K)

    const int crow = lane >> 2;
    const int ccol = (lane & 3) * 2;
    const int region = bn >> 11;        // 0 = q, 1 = k, 2 = v
    const int h = (bn >> 7) & 15;

    if (region == 2) {
#pragma unroll
        for (int tm = 0; tm < 2; tm++) {
#pragma unroll
            for (int t = 0; t < 8; t++) {
                int d = warp_n * 64 + t * 8 + ccol;
#pragma unroll
                for (int rh = 0; rh < 2; rh++) {
                    int row = bm + warp_m * 32 + tm * 16 + crow + rh * 8;
                    float v0 = acc[tm][t][rh * 2 + 0];
                    float v1 = acc[tm][t][rh * 2 + 1];
                    int b = row >> 11, n = row & (NN - 1);
                    size_t dst = ((size_t)(b * HN + h) * NN + n) * HDIM + d;
                    __half h0 = __float2half_rn(v0), h1 = __float2half_rn(v1);
                    __half2 H; H.x = h0; H.y = h1;
                    __half2 L;
                    L.x = __float2half_rn(v0 - __half2float(h0));
                    L.y = __float2half_rn(v1 - __half2float(h1));
                    *(uint32_t*)(Vhi + dst) = *(uint32_t*)&H;
                    *(uint32_t*)(Vlo + dst) = *(uint32_t*)&L;
                }
            }
        }
    } else {
#pragma unroll
        for (int tm = 0; tm < 2; tm++) {
            float p0 = 0.f, p1 = 0.f;
#pragma unroll
            for (int t = 0; t < 8; t++) {
                p0 = fmaf(acc[tm][t][0], acc[tm][t][0], p0);
                p0 = fmaf(acc[tm][t][1], acc[tm][t][1], p0);
                p1 = fmaf(acc[tm][t][2], acc[tm][t][2], p1);
                p1 = fmaf(acc[tm][t][3], acc[tm][t][3], p1);
            }
            p0 += __shfl_xor_sync(0xffffffffu, p0, 1);
            p0 += __shfl_xor_sync(0xffffffffu, p0, 2);
            p1 += __shfl_xor_sync(0xffffffffu, p1, 1);
            p1 += __shfl_xor_sync(0xffffffffu, p1, 2);
            if ((lane & 3) == 0) {
                red[warp_m * 32 + tm * 16 + (lane >> 2)][warp_n] = p0;
                red[warp_m * 32 + tm * 16 + (lane >> 2) + 8][warp_n] = p1;
            }
        }
        __syncthreads();

        const float* gam = (region == 0) ? qg : kgm;
        const float qs = (region == 0) ? QSCALE : 1.0f;
        __nv_bfloat16* Dhi = (region == 0) ? Qhi : Khi;
        __nv_bfloat16* Dlo = (region == 0) ? Qlo : Klo;

#pragma unroll
        for (int tm = 0; tm < 2; tm++) {
#pragma unroll
            for (int rh = 0; rh < 2; rh++) {
                int lrow = warp_m * 32 + tm * 16 + crow + rh * 8;
                int row = bm + lrow;
                float tot = red[lrow][0] + red[lrow][1];
                float rinv = rsqrtf(tot * (1.0f / HDIM) + EPSV) * qs;
                int b = row >> 11, n = row & (NN - 1);
                const float* fr = freqs + (size_t)row * 128;
                size_t obase = ((size_t)(b * HN + h) * NN + n) * HDIM;
#pragma unroll
                for (int t = 0; t < 8; t++) {
                    int d = warp_n * 64 + t * 8 + ccol;
                    int i = d >> 1;
                    float x0 = acc[tm][t][rh * 2 + 0] * rinv * gam[d];
                    float x1 = acc[tm][t][rh * 2 + 1] * rinv * gam[d + 1];
                    float cs = fr[i * 2 + 0], sn = fr[i * 2 + 1];
                    float y0 = x0 * cs - x1 * sn;
                    float y1 = x0 * sn + x1 * cs;
                    uint32_t hi, lo;
                    split2(y0, y1, hi, lo);
                    *(uint32_t*)(Dhi + obase + d) = hi;
                    *(uint32_t*)(Dlo + obase + d) = lo;
                }
            }
        }
    }
}

// ============================================================================
// Flash attention: Q persistent in smem, 64-key KV tiles double-buffered,
// LOADERS FIXED (16 chunks/row — full 128 columns; R9/R12 loaded only 64).
// ============================================================================
#define SK 136
#define QMAT 34816                        // 128 x 136 x 2
#define KVM 17408                         // 64 x 136 x 2
#define KVSTAGE (4 * KVM)                 // 69632
#define ATT_SMEM (2 * QMAT + 2 * KVSTAGE) // 208896

__global__ void __launch_bounds__(256, 1) attn_mma(
    const __nv_bfloat16* __restrict__ Qh, const __nv_bfloat16* __restrict__ Ql,
    const __nv_bfloat16* __restrict__ Kh, const __nv_bfloat16* __restrict__ Kl,
    const __half* __restrict__ Vh, const __half* __restrict__ Vl,
    __nv_bfloat16* __restrict__ Ohi, __nv_bfloat16* __restrict__ Olo)
{
    extern __shared__ __align__(128) char smA[];
    const uint32_t sbase = smem_u32(smA);
    const uint32_t sQh = sbase, sQl = sbase + QMAT;
    const uint32_t kvbase[2] = {sbase + 2 * QMAT, sbase + 2 * QMAT + KVSTAGE};

    const int tid = threadIdx.x;
    const int lane = tid & 31;
    const int wid = tid >> 5;
    const int qt = blockIdx.x & 15;
    const int bh = blockIdx.x >> 4;

    const size_t seqbase = (size_t)bh * NN * HDIM;
    const __nv_bfloat16* qh_p = Qh + seqbase + (size_t)qt * 128 * HDIM;
    const __nv_bfloat16* ql_p = Ql + seqbase + (size_t)qt * 128 * HDIM;

    // KV tile loader: 4 matrices x 64 rows x 16 chunks = 4096 chunks, 16/thread
    auto load_kv = [&](int t64, uint32_t base) {
        const __nv_bfloat16* kh_p = Kh + seqbase + (size_t)t64 * 64 * HDIM;
        const __nv_bfloat16* kl_p = Kl + seqbase + (size_t)t64 * 64 * HDIM;
        const __half* vh_p = Vh + seqbase + (size_t)t64 * 64 * HDIM;
        const __half* vl_p = Vl + seqbase + (size_t)t64 * 64 * HDIM;
#pragma unroll
        for (int t = 0; t < 16; t++) {
            int idx = tid + t * 256;
            int mat = idx >> 10;
            int j = idx & 1023;
            int row = j >> 4, c8 = j & 15;
            uint32_t dst = base + mat * KVM + (row * SK + c8 * 8) * 2;
            int go = row * HDIM + c8 * 8;
            const void* src = (mat == 0) ? (const void*)(kh_p + go)
                            : (mat == 1) ? (const void*)(kl_p + go)
                            : (mat == 2) ? (const void*)(vh_p + go)
                            :              (const void*)(vl_p + go);
            cp_async16(dst, src);
        }
        CP_COMMIT();
    };

    // prologue: Q (2 matrices x 128 rows x 16 chunks = 4096 chunks, 16/thread)
    {
#pragma unroll
        for (int t = 0; t < 16; t++) {
            int idx = tid + t * 256;
            int mat = idx >> 11;
            int j = idx & 2047;
            int row = j >> 4, c8 = j & 15;
            uint32_t off = (row * SK + c8 * 8) * 2 + mat * QMAT;
            const __nv_bfloat16* src = (mat ? ql_p : qh_p) + row * HDIM + c8 * 8;
            cp_async16(sQh + off, src);
        }
        CP_COMMIT();
    }
    load_kv(0, kvbase[0]);
    load_kv(1, kvbase[1]);

    float o[16][4];
#pragma unroll
    for (int t = 0; t < 16; t++)
#pragma unroll
        for (int j = 0; j < 4; j++) o[t][j] = 0.f;
    float mrow0 = -1e30f, mrow1 = -1e30f, lrow0 = 0.f, lrow1 = 0.f;

    const uint32_t ones2 = 0x3C003C00u;
    const uint32_t bones[2] = {ones2, ones2};

    const int a_r = wid * 16 + (lane & 15);
    const int a_c8 = lane >> 4;
    const int kb_r = (lane & 7) + (lane >> 4) * 8;
    const int kb_c8 = (lane >> 3) & 1;
    const int v_r = lane & 15;
    const int v_c8 = lane >> 4;

    for (int tt = 0; tt < 32; tt++) {
        if (tt < 31) { CP_WAIT(1); } else { CP_WAIT(0); }
        __syncthreads();

        const uint32_t kvb = kvbase[tt & 1];
        const uint32_t tKh = kvb, tKl = kvb + KVM;
        const uint32_t tVh = kvb + 2 * KVM, tVl = kvb + 3 * KVM;

        // ---- S = Q K^T over 64 keys (bf16, 3 passes) ----
        float s[8][4];
#pragma unroll
        for (int t = 0; t < 8; t++)
#pragma unroll
            for (int j = 0; j < 4; j++) s[t][j] = 0.f;

#pragma unroll
        for (int kk = 0; kk < 8; kk++) {
            uint32_t qa[4], qb[4];
            uint32_t aoff = (a_r * SK + kk * 16 + a_c8 * 8) * 2;
            ldsm_x4(qa, sQh + aoff);
            ldsm_x4(qb, sQl + aoff);
#pragma unroll
            for (int nt = 0; nt < 4; nt++) {
                uint32_t kf[4], kg2[4];
                uint32_t boff = ((nt * 16 + kb_r) * SK + kk * 16 + kb_c8 * 8) * 2;
                ldsm_x4(kf, tKh + boff);
                ldsm_x4(kg2, tKl + boff);
                mma_bf16(s[2 * nt], qa, kf);
                mma_bf16(s[2 * nt], qa, kg2);
                mma_bf16(s[2 * nt], qb, kf);
                mma_bf16(s[2 * nt + 1], qa, kf + 2);
                mma_bf16(s[2 * nt + 1], qa, kg2 + 2);
                mma_bf16(s[2 * nt + 1], qb, kf + 2);
            }
        }

        // ---- online softmax ----
        float tm0 = -1e30f, tm1 = -1e30f;
#pragma unroll
        for (int t = 0; t < 8; t++) {
            tm0 = fmaxf(tm0, fmaxf(s[t][0], s[t][1]));
            tm1 = fmaxf(tm1, fmaxf(s[t][2], s[t][3]));
        }
        tm0 = fmaxf(tm0, __shfl_xor_sync(0xffffffffu, tm0, 1));
        tm0 = fmaxf(tm0, __shfl_xor_sync(0xffffffffu, tm0, 2));
        tm1 = fmaxf(tm1, __shfl_xor_sync(0xffffffffu, tm1, 1));
        tm1 = fmaxf(tm1, __shfl_xor_sync(0xffffffffu, tm1, 2));
        float mn0 = fmaxf(mrow0, tm0), mn1 = fmaxf(mrow1, tm1);
        float fac0 = __expf(mrow0 - mn0), fac1 = __expf(mrow1 - mn1);
        mrow0 = mn0; mrow1 = mn1;

        const float mnl0 = mn0 * LOG2E, mnl1 = mn1 * LOG2E;
        uint32_t ph[8][2];
#pragma unroll
        for (int t = 0; t < 8; t++) {
            float e0 = fmaf(s[t][0], LOG2E, -mnl0);
            float e1 = fmaf(s[t][1], LOG2E, -mnl0);
            float e2 = fmaf(s[t][2], LOG2E, -mnl1);
            float e3 = fmaf(s[t][3], LOG2E, -mnl1);
            ph[t][0] = h2exp2(packh2(e0, e1));
            ph[t][1] = h2exp2(packh2(e2, e3));
        }

        // ---- row sums via P * ones ----
        float lacc[4] = {0.f, 0.f, 0.f, 0.f};
#pragma unroll
        for (int kk = 0; kk < 4; kk++) {
            uint32_t ah[4] = {ph[2 * kk][0], ph[2 * kk][1],
                              ph[2 * kk + 1][0], ph[2 * kk + 1][1]};
            mma_f16(lacc, ah, bones);
        }
        lrow0 = lrow0 * fac0 + lacc[0];
        lrow1 = lrow1 * fac1 + lacc[2];

#pragma unroll
        for (int t = 0; t < 16; t++) {
            o[t][0] *= fac0; o[t][1] *= fac0;
            o[t][2] *= fac1; o[t][3] *= fac1;
        }

        // ---- O += P V (fp16, 2 passes) ----
#pragma unroll
        for (int kk = 0; kk < 4; kk++) {
            uint32_t ah[4] = {ph[2 * kk][0], ph[2 * kk][1],
                              ph[2 * kk + 1][0], ph[2 * kk + 1][1]};
#pragma unroll
            for (int nt = 0; nt < 8; nt++) {
                uint32_t vf[4], vg[4];
                uint32_t voff = ((kk * 16 + v_r) * SK + nt * 16 + v_c8 * 8) * 2;
                ldsm_x4_t(vf, tVh + voff);
                ldsm_x4_t(vg, tVl + voff);
                mma_f16(o[2 * nt], ah, vf);
                mma_f16(o[2 * nt], ah, vg);
                mma_f16(o[2 * nt + 1], ah, vf + 2);
                mma_f16(o[2 * nt + 1], ah, vg + 2);
            }
        }

        // all threads done reading this buffer; refill it with tile tt+2
        __syncthreads();
        if (tt + 2 < 32) load_kv(tt + 2, kvbase[tt & 1]);
    }

    const int b = bh >> 4, h = bh & 15;
    const int n0 = qt * 128 + wid * 16 + (lane >> 2);
    const float inv0 = 1.0f / lrow0, inv1 = 1.0f / lrow1;
    const size_t grow0 = (size_t)(b * NN + n0) * DIMM;
    const size_t grow1 = (size_t)(b * NN + n0 + 8) * DIMM;
#pragma unroll
    for (int t = 0; t < 16; t++) {
        int col = h * HDIM + t * 8 + (lane & 3) * 2;
        uint32_t hi0, lo0, hi1, lo1;
        split2(o[t][0] * inv0, o[t][1] * inv0, hi0, lo0);
        split2(o[t][2] * inv1, o[t][3] * inv1, hi1, lo1);
        *(uint32_t*)(Ohi + grow0 + col) = hi0;
        *(uint32_t*)(Olo + grow0 + col) = lo0;
        *(uint32_t*)(Ohi + grow1 + col) = hi1;
        *(uint32_t*)(Olo + grow1 + col) = lo1;
    }
}

// ============================================================================
// Launch
// ============================================================================
extern "C" void kernel_launch(void* const* d_in, const int* in_sizes, int n_in,
                              void* d_out, int out_size)
{
    const float* x     = (const float*)d_in[0];
    const float* Wqkv  = (const float*)d_in[1];
    const float* qg    = (const float*)d_in[2];
    const float* kg    = (const float*)d_in[3];
    const float* Wout  = (const float*)d_in[4];
    const float* freqs = (const float*)d_in[5];
    float* out = (float*)d_out;

    __nv_bfloat16 *qhi, *qlo, *khi, *klo;
    __half *vhi, *vlo;
    __nv_bfloat16 *xhi, *xlo, *w1hi, *w1lo, *w2hi, *w2lo, *aohi, *aolo;
    cudaGetSymbolAddress((void**)&qhi, g_qhi);
    cudaGetSymbolAddress((void**)&qlo, g_qlo);
    cudaGetSymbolAddress((void**)&khi, g_khi);
    cudaGetSymbolAddress((void**)&klo, g_klo);
    cudaGetSymbolAddress((void**)&vhi, g_vhi);
    cudaGetSymbolAddress((void**)&vlo, g_vlo);
    cudaGetSymbolAddress((void**)&xhi, g_xhi);
    cudaGetSymbolAddress((void**)&xlo, g_xlo);
    cudaGetSymbolAddress((void**)&w1hi, g_w1hi);
    cudaGetSymbolAddress((void**)&w1lo, g_w1lo);
    cudaGetSymbolAddress((void**)&w2hi, g_w2hi);
    cudaGetSymbolAddress((void**)&w2lo, g_w2lo);
    cudaGetSymbolAddress((void**)&aohi, g_aohi);
    cudaGetSymbolAddress((void**)&aolo, g_aolo);

    cudaFuncSetAttribute(gemm_mma_split,
                         cudaFuncAttributeMaxDynamicSharedMemorySize, GEMM_SMEM);
    cudaFuncSetAttribute(gemm_qkv_fused,
                         cudaFuncAttributeMaxDynamicSharedMemorySize, GEMM_SMEM);
    cudaFuncSetAttribute(attn_mma,
                         cudaFuncAttributeMaxDynamicSharedMemorySize, ATT_SMEM);

    // splits of inputs
    {
        int n4x = (MROWS * DIMM) / 4;
        split_bf16<<<n4x / 256, 256>>>(x, xhi, xlo, n4x);
        int n4w1 = (E3 * DIMM) / 4;
        split_bf16<<<n4w1 / 256, 256>>>(Wqkv, w1hi, w1lo, n4w1);
        int n4w2 = (DIMM * DIMM) / 4;
        split_bf16<<<n4w2 / 256, 256>>>(Wout, w2hi, w2lo, n4w2);
    }
    // 1. QKV GEMM with fused RMSNorm + RoPE + split scatter
    {
        dim3 grid(E3 / 128, MROWS / 128);
        gemm_qkv_fused<<<grid, 256, GEMM_SMEM>>>(
            xhi, xlo, w1hi, w1lo, qg, kg, freqs,
            qhi, qlo, khi, klo, vhi, vlo);
    }
    // 2. Attention
    attn_mma<<<BB * HN * 16, 256, ATT_SMEM>>>(qhi, qlo, khi, klo, vhi, vlo,
                                              aohi, aolo);
    // 3. out GEMM
    {
        dim3 grid(DIMM / 128, MROWS / 128);
        gemm_mma_split<<<grid, 256, GEMM_SMEM>>>(aohi, aolo, w2hi, w2lo, out, DIMM, DIMM);
    }
}